// round 1
// baseline (speedup 1.0000x reference)
#include <cuda_runtime.h>
#include <cuda_bf16.h>
#include <math.h>

// ---------------- problem constants ----------------
#define BB 4
#define QQ 600
#define LL 2048
#define DD 256
#define HH 8
#define HD 32
#define DFF 2048
#define KD 32
#define SCALE 0.17677669529663687f   // 32^-0.5

// ---------------- scratch (device globals) ----------------
__device__ float s_qkv [BB*QQ*3*DD];     // 2400 x 768
__device__ float s_sa  [BB*QQ*DD];
__device__ float s_tmp [BB*QQ*DD];
__device__ float s_x1  [BB*QQ*DD];
__device__ float s_x2  [BB*QQ*DD];
__device__ float s_q   [BB*QQ*DD];
__device__ float s_k   [BB*LL*DD];
__device__ float s_v   [BB*LL*DD];
__device__ float s_bias[BB*LL*QQ];       // transposed: [B, L, Q]
__device__ float s_ca  [BB*QQ*DD];
__device__ float s_ffn [BB*QQ*DFF];

// ---------------- tiled SGEMM: C[M,N] = A[M,K] @ W[N,K]^T + bias, opt ReLU ----
#define TBM 64
#define TBN 64
#define TBK 16

__global__ __launch_bounds__(256) void gemm_kernel(
    const float* __restrict__ A, const float* __restrict__ W,
    const float* __restrict__ bias, float* __restrict__ C,
    int M, int N, int K, int relu)
{
    __shared__ float As[TBK][TBM + 1];
    __shared__ float Bs[TBK][TBN + 1];

    const int tid = threadIdx.x;          // 0..255
    const int tx = tid & 15;              // 0..15
    const int ty = tid >> 4;              // 0..15
    const int m0 = blockIdx.y * TBM;
    const int n0 = blockIdx.x * TBN;

    const int lr  = tid >> 2;             // 0..63
    const int lc4 = (tid & 3) << 2;       // 0,4,8,12

    float acc[4][4] = {};

    for (int k0 = 0; k0 < K; k0 += TBK) {
        // A tile (guard rows)
        float4 av = make_float4(0.f, 0.f, 0.f, 0.f);
        int arow = m0 + lr;
        if (arow < M)
            av = *reinterpret_cast<const float4*>(A + (size_t)arow * K + k0 + lc4);
        As[lc4 + 0][lr] = av.x; As[lc4 + 1][lr] = av.y;
        As[lc4 + 2][lr] = av.z; As[lc4 + 3][lr] = av.w;
        // W tile (N always multiple of 64 here)
        int wrow = n0 + lr;
        float4 wv = *reinterpret_cast<const float4*>(W + (size_t)wrow * K + k0 + lc4);
        Bs[lc4 + 0][lr] = wv.x; Bs[lc4 + 1][lr] = wv.y;
        Bs[lc4 + 2][lr] = wv.z; Bs[lc4 + 3][lr] = wv.w;
        __syncthreads();

        #pragma unroll
        for (int kk = 0; kk < TBK; kk++) {
            float ar[4], br[4];
            #pragma unroll
            for (int i = 0; i < 4; i++) ar[i] = As[kk][ty * 4 + i];
            #pragma unroll
            for (int j = 0; j < 4; j++) br[j] = Bs[kk][tx * 4 + j];
            #pragma unroll
            for (int i = 0; i < 4; i++)
                #pragma unroll
                for (int j = 0; j < 4; j++)
                    acc[i][j] += ar[i] * br[j];
        }
        __syncthreads();
    }

    #pragma unroll
    for (int i = 0; i < 4; i++) {
        int r = m0 + ty * 4 + i;
        if (r >= M) continue;
        #pragma unroll
        for (int j = 0; j < 4; j++) {
            int c = n0 + tx * 4 + j;
            float v = acc[i][j] + bias[c];
            if (relu) v = fmaxf(v, 0.f);
            C[(size_t)r * N + c] = v;
        }
    }
}

// ---------------- residual-add + LayerNorm over D=256 ----------------
__global__ __launch_bounds__(256) void ln_kernel(
    const float* __restrict__ A, const float* __restrict__ R,
    const float* __restrict__ g, const float* __restrict__ bt,
    float* __restrict__ out)
{
    const int row = blockIdx.x;
    const int tid = threadIdx.x;
    float v = A[(size_t)row * DD + tid];
    if (R) v += R[(size_t)row * DD + tid];

    __shared__ float red[256];
    red[tid] = v;
    __syncthreads();
    for (int s = 128; s > 0; s >>= 1) {
        if (tid < s) red[tid] += red[tid + s];
        __syncthreads();
    }
    float mean = red[0] * (1.f / DD);
    __syncthreads();
    float c = v - mean;
    red[tid] = c * c;
    __syncthreads();
    for (int s = 128; s > 0; s >>= 1) {
        if (tid < s) red[tid] += red[tid + s];
        __syncthreads();
    }
    float var = red[0] * (1.f / DD);
    out[(size_t)row * DD + tid] = c * rsqrtf(var + 1e-5f) * g[tid] + bt[tid];
}

// ---------------- GASA geometric bias: biasT[b][l][q] ----------------
__global__ __launch_bounds__(128) void gasa_bias_kernel(
    const float* __restrict__ qpos, const float* __restrict__ mpos,
    const float* __restrict__ w1, const float* __restrict__ b1,
    const float* __restrict__ w2, const float* __restrict__ b2,
    float* __restrict__ biasT)
{
    const int b = blockIdx.z;
    const int l = blockIdx.y;
    const int q = blockIdx.x * 128 + threadIdx.x;

    __shared__ float sw1[KD], sb1[KD], sw2[KD], smp[3];
    if (threadIdx.x < KD) {
        sw1[threadIdx.x] = w1[threadIdx.x];
        sb1[threadIdx.x] = b1[threadIdx.x];
        sw2[threadIdx.x] = w2[threadIdx.x];
    }
    if (threadIdx.x < 3)
        smp[threadIdx.x] = mpos[((size_t)b * LL + l) * 3 + threadIdx.x];
    __syncthreads();

    if (q >= QQ) return;
    const float* qp = qpos + ((size_t)b * QQ + q) * 3;
    float dx = qp[0] - smp[0], dy = qp[1] - smp[1], dz = qp[2] - smp[2];
    float d2 = dx * dx + dy * dy + dz * dz;
    float dist = sqrtf(fmaxf(d2, 0.f));

    float s = 0.f;
    #pragma unroll
    for (int k = 0; k < KD; k++) {
        float h = fmaxf(dist * sw1[k] + sb1[k], 0.f);
        s += h * sw2[k];
    }
    s += b2[0];
    s = fminf(fmaxf(s, -10.f), 0.f);
    biasT[((size_t)b * LL + l) * QQ + q] = s;
}

// ---------------- fused attention (flash-style, 1 thread per (b,h,q)) ------
// Q rows per batch = QQ. K/V rows per batch = Lk. biasT optional ([B,Lk,Q]).
__global__ __launch_bounds__(128) void attn_kernel(
    const float* __restrict__ Qp, int qstride,
    const float* __restrict__ Kp, const float* __restrict__ Vp, int kvstride,
    const float* __restrict__ biasT, const float* __restrict__ betap,
    int Lk, float* __restrict__ out)
{
    const int b = blockIdx.z, h = blockIdx.y;
    const int tid = threadIdx.x;
    const int q = blockIdx.x * 128 + tid;
    const bool active = (q < QQ);
    const float beta = (biasT != nullptr) ? *betap : 0.f;

    float qv[HD];
    if (active) {
        const float* qptr = Qp + ((size_t)(b * QQ + q)) * qstride + h * HD;
        #pragma unroll
        for (int d = 0; d < HD; d++) qv[d] = qptr[d];
    }
    float acc[HD];
    #pragma unroll
    for (int d = 0; d < HD; d++) acc[d] = 0.f;
    float m = -INFINITY, lsum = 0.f;

    __shared__ float Ks[8][HD];
    __shared__ float Vs[8][HD];
    __shared__ float Bsm[8][128];

    for (int l0 = 0; l0 < Lk; l0 += 8) {
        // cooperative K/V chunk load: 2 elements per thread per array
        {
            int li = tid >> 5, di = tid & 31;
            size_t row = (size_t)(b * Lk + l0 + li);
            Ks[li][di] = Kp[row * kvstride + h * HD + di];
            Vs[li][di] = Vp[row * kvstride + h * HD + di];
            li = (tid + 128) >> 5; di = tid & 31;
            row = (size_t)(b * Lk + l0 + li);
            Ks[li][di] = Kp[row * kvstride + h * HD + di];
            Vs[li][di] = Vp[row * kvstride + h * HD + di];
        }
        if (biasT) {
            #pragma unroll
            for (int li = 0; li < 8; li++)
                Bsm[li][tid] = active
                    ? biasT[((size_t)(b * Lk + l0 + li)) * QQ + q] : 0.f;
        }
        __syncthreads();

        if (active) {
            #pragma unroll
            for (int li = 0; li < 8; li++) {
                float s = 0.f;
                #pragma unroll
                for (int d = 0; d < HD; d++) s += qv[d] * Ks[li][d];
                s *= SCALE;
                if (biasT) s += beta * Bsm[li][tid];
                if (s <= m) {
                    float p = __expf(s - m);
                    lsum += p;
                    #pragma unroll
                    for (int d = 0; d < HD; d++) acc[d] += p * Vs[li][d];
                } else {
                    float corr = __expf(m - s);
                    lsum = lsum * corr + 1.f;
                    #pragma unroll
                    for (int d = 0; d < HD; d++)
                        acc[d] = acc[d] * corr + Vs[li][d];
                    m = s;
                }
            }
        }
        __syncthreads();
    }

    if (active) {
        float inv = 1.f / lsum;
        float* optr = out + ((size_t)(b * QQ + q)) * DD + h * HD;
        #pragma unroll
        for (int d = 0; d < HD; d++) optr[d] = acc[d] * inv;
    }
}

// ---------------- host launcher ----------------
static inline int cdiv(int a, int b) { return (a + b - 1) / b; }

extern "C" void kernel_launch(void* const* d_in, const int* in_sizes, int n_in,
                              void* d_out, int out_size)
{
    const float* queries   = (const float*)d_in[0];
    const float* memory    = (const float*)d_in[1];
    const float* memory_pos= (const float*)d_in[2];
    const float* query_pos = (const float*)d_in[3];
    const float* sa_in_w   = (const float*)d_in[4];
    const float* sa_in_b   = (const float*)d_in[5];
    const float* sa_out_w  = (const float*)d_in[6];
    const float* sa_out_b  = (const float*)d_in[7];
    const float* norm1_g   = (const float*)d_in[8];
    const float* norm1_b   = (const float*)d_in[9];
    const float* q_w       = (const float*)d_in[10];
    const float* q_b       = (const float*)d_in[11];
    const float* k_w       = (const float*)d_in[12];
    const float* k_b       = (const float*)d_in[13];
    const float* v_w       = (const float*)d_in[14];
    const float* v_b       = (const float*)d_in[15];
    const float* o_w       = (const float*)d_in[16];
    const float* o_b       = (const float*)d_in[17];
    const float* norm2_g   = (const float*)d_in[18];
    const float* norm2_b   = (const float*)d_in[19];
    const float* beta      = (const float*)d_in[20];
    const float* dk_w1     = (const float*)d_in[21];
    const float* dk_b1     = (const float*)d_in[22];
    const float* dk_w2     = (const float*)d_in[23];
    const float* dk_b2     = (const float*)d_in[24];
    const float* ffn_w1    = (const float*)d_in[25];
    const float* ffn_b1    = (const float*)d_in[26];
    const float* ffn_w2    = (const float*)d_in[27];
    const float* ffn_b2    = (const float*)d_in[28];
    const float* norm3_g   = (const float*)d_in[29];
    const float* norm3_b   = (const float*)d_in[30];

    float *g_qkv, *g_sa, *g_tmp, *g_x1, *g_x2, *g_q, *g_k, *g_v, *g_bias, *g_ca, *g_ffn;
    cudaGetSymbolAddress((void**)&g_qkv,  s_qkv);
    cudaGetSymbolAddress((void**)&g_sa,   s_sa);
    cudaGetSymbolAddress((void**)&g_tmp,  s_tmp);
    cudaGetSymbolAddress((void**)&g_x1,   s_x1);
    cudaGetSymbolAddress((void**)&g_x2,   s_x2);
    cudaGetSymbolAddress((void**)&g_q,    s_q);
    cudaGetSymbolAddress((void**)&g_k,    s_k);
    cudaGetSymbolAddress((void**)&g_v,    s_v);
    cudaGetSymbolAddress((void**)&g_bias, s_bias);
    cudaGetSymbolAddress((void**)&g_ca,   s_ca);
    cudaGetSymbolAddress((void**)&g_ffn,  s_ffn);

    const int Mq = BB * QQ;   // 2400
    const int Mm = BB * LL;   // 8192

    // 1) self-attn packed in-proj: [2400,768]
    gemm_kernel<<<dim3(3 * DD / TBN, cdiv(Mq, TBM)), 256>>>(
        queries, sa_in_w, sa_in_b, g_qkv, Mq, 3 * DD, DD, 0);

    // 2) self-attention (no bias)
    attn_kernel<<<dim3(cdiv(QQ, 128), HH, BB), 128>>>(
        g_qkv, 3 * DD, g_qkv + DD, g_qkv + 2 * DD, 3 * DD,
        nullptr, nullptr, QQ, g_sa);

    // 3) SA out-proj + LN1
    gemm_kernel<<<dim3(DD / TBN, cdiv(Mq, TBM)), 256>>>(
        g_sa, sa_out_w, sa_out_b, g_tmp, Mq, DD, DD, 0);
    ln_kernel<<<Mq, 256>>>(queries, g_tmp, norm1_g, norm1_b, g_x1);

    // 4) cross projections
    gemm_kernel<<<dim3(DD / TBN, cdiv(Mq, TBM)), 256>>>(
        g_x1, q_w, q_b, g_q, Mq, DD, DD, 0);
    gemm_kernel<<<dim3(DD / TBN, cdiv(Mm, TBM)), 256>>>(
        memory, k_w, k_b, g_k, Mm, DD, DD, 0);
    gemm_kernel<<<dim3(DD / TBN, cdiv(Mm, TBM)), 256>>>(
        memory, v_w, v_b, g_v, Mm, DD, DD, 0);

    // 5) GASA geometric bias (transposed [B,L,Q])
    gasa_bias_kernel<<<dim3(cdiv(QQ, 128), LL, BB), 128>>>(
        query_pos, memory_pos, dk_w1, dk_b1, dk_w2, dk_b2, g_bias);

    // 6) cross-attention with bias
    attn_kernel<<<dim3(cdiv(QQ, 128), HH, BB), 128>>>(
        g_q, DD, g_k, g_v, DD, g_bias, beta, LL, g_ca);

    // 7) O proj + LN2
    gemm_kernel<<<dim3(DD / TBN, cdiv(Mq, TBM)), 256>>>(
        g_ca, o_w, o_b, g_tmp, Mq, DD, DD, 0);
    ln_kernel<<<Mq, 256>>>(g_x1, g_tmp, norm2_g, norm2_b, g_x2);

    // 8) FFN + LN3 -> output
    gemm_kernel<<<dim3(DFF / TBN, cdiv(Mq, TBM)), 256>>>(
        g_x2, ffn_w1, ffn_b1, g_ffn, Mq, DFF, DD, 1);
    gemm_kernel<<<dim3(DD / TBN, cdiv(Mq, TBM)), 256>>>(
        g_ffn, ffn_w2, ffn_b2, g_tmp, Mq, DD, DFF, 0);
    ln_kernel<<<Mq, 256>>>(g_x2, g_tmp, norm3_g, norm3_b, (float*)d_out);
}

// round 2
// speedup vs baseline: 1.5565x; 1.5565x over previous
#include <cuda_runtime.h>
#include <cuda_bf16.h>
#include <math.h>

// ---------------- problem constants ----------------
#define BB 4
#define QQ 600
#define LL 2048
#define DD 256
#define HH 8
#define HD 32
#define DFF 2048
#define KD 32
#define SCALE 0.17677669529663687f   // 32^-0.5
#define QT 5                         // ceil(600/128) query tiles

typedef unsigned long long u64;

// ---------------- f32x2 packed-math helpers (sm_103a FFMA2) ----------------
__device__ __forceinline__ u64 pk2(float lo, float hi) {
    u64 r;
    asm("mov.b64 %0, {%1, %2};" : "=l"(r) : "f"(lo), "f"(hi));
    return r;
}
__device__ __forceinline__ void upk2(u64 v, float& lo, float& hi) {
    asm("mov.b64 {%0, %1}, %2;" : "=f"(lo), "=f"(hi) : "l"(v));
}
__device__ __forceinline__ void fma2(u64& d, u64 a, u64 b) {
    asm("fma.rn.f32x2 %0, %1, %2, %0;" : "+l"(d) : "l"(a), "l"(b));
}
__device__ __forceinline__ void mul2(u64& d, u64 a) {
    asm("mul.rn.f32x2 %0, %0, %1;" : "+l"(d) : "l"(a));
}

// ---------------- scratch (device globals) ----------------
__device__ float s_qkv [BB*QQ*3*DD];
__device__ float s_sa  [BB*QQ*DD];
__device__ float s_tmp [BB*QQ*DD];
__device__ float s_x1  [BB*QQ*DD];
__device__ float s_x2  [BB*QQ*DD];
__device__ float s_q   [BB*QQ*DD];
__device__ float s_k   [BB*LL*DD];
__device__ float s_v   [BB*LL*DD];
__device__ float s_bias[BB*LL*QQ];           // beta * clipped bias, [B, L, Q]
__device__ float s_ca  [BB*QQ*DD];
__device__ float s_ffn [BB*QQ*DFF];
// split-attention partials (max 8 splits)
__device__ float s_pm  [BB*HH*8*QQ];
__device__ float s_pl  [BB*HH*8*QQ];
__device__ float s_pacc[BB*HH*8*QQ*HD];

// ---------------- SGEMM with FFMA2: C[M,N] = A @ W^T + bias (opt relu) -----
#define GM 64
#define GN 64
#define GK 16

__global__ __launch_bounds__(128) void gemm2_kernel(
    const float* __restrict__ A, const float* __restrict__ W,
    const float* __restrict__ bias, float* __restrict__ C,
    int M, int N, int K, int relu)
{
    __shared__ __align__(16) float As[GK][GM + 4];  // stride 68 floats = 272B (16B mult)
    __shared__ __align__(16) float Bs[GK][GN + 4];

    const int tid = threadIdx.x;     // 0..127
    const int tx = tid & 7;          // col group: cols tx*8 .. tx*8+7
    const int ty = tid >> 3;         // row group: rows ty*4 .. ty*4+3
    const int m0 = blockIdx.y * GM;
    const int n0 = blockIdx.x * GN;

    const int lr = tid >> 2;         // 0..31
    const int kc = (tid & 3) * 4;    // 0,4,8,12

    u64 acc[4][4];
    #pragma unroll
    for (int i = 0; i < 4; i++)
        #pragma unroll
        for (int j = 0; j < 4; j++) acc[i][j] = 0ull;

    for (int k0 = 0; k0 < K; k0 += GK) {
        // A tile: rows lr and lr+32, cols kc..kc+3, store transposed
        #pragma unroll
        for (int half = 0; half < 2; half++) {
            int r = lr + half * 32;
            int arow = m0 + r;
            float4 av = make_float4(0.f, 0.f, 0.f, 0.f);
            if (arow < M)
                av = *reinterpret_cast<const float4*>(A + (size_t)arow * K + k0 + kc);
            As[kc + 0][r] = av.x; As[kc + 1][r] = av.y;
            As[kc + 2][r] = av.z; As[kc + 3][r] = av.w;
            int wrow = n0 + r;   // N always multiple of 64
            float4 wv = *reinterpret_cast<const float4*>(W + (size_t)wrow * K + k0 + kc);
            Bs[kc + 0][r] = wv.x; Bs[kc + 1][r] = wv.y;
            Bs[kc + 2][r] = wv.z; Bs[kc + 3][r] = wv.w;
        }
        __syncthreads();

        #pragma unroll
        for (int kk = 0; kk < GK; kk++) {
            float4 av = *reinterpret_cast<const float4*>(&As[kk][ty * 4]);
            ulonglong2 b0 = *reinterpret_cast<const ulonglong2*>(&Bs[kk][tx * 8]);
            ulonglong2 b1 = *reinterpret_cast<const ulonglong2*>(&Bs[kk][tx * 8 + 4]);
            u64 bb[4] = { b0.x, b0.y, b1.x, b1.y };
            u64 aa[4] = { pk2(av.x, av.x), pk2(av.y, av.y),
                          pk2(av.z, av.z), pk2(av.w, av.w) };
            #pragma unroll
            for (int i = 0; i < 4; i++)
                #pragma unroll
                for (int j = 0; j < 4; j++)
                    fma2(acc[i][j], aa[i], bb[j]);
        }
        __syncthreads();
    }

    #pragma unroll
    for (int i = 0; i < 4; i++) {
        int r = m0 + ty * 4 + i;
        if (r >= M) continue;
        #pragma unroll
        for (int j = 0; j < 4; j++) {
            float lo, hi;
            upk2(acc[i][j], lo, hi);
            int c0 = n0 + tx * 8 + 2 * j;
            float v0 = lo + bias[c0], v1 = hi + bias[c0 + 1];
            if (relu) { v0 = fmaxf(v0, 0.f); v1 = fmaxf(v1, 0.f); }
            C[(size_t)r * N + c0]     = v0;
            C[(size_t)r * N + c0 + 1] = v1;
        }
    }
}

// ---------------- residual-add + LayerNorm over D=256 ----------------
__global__ __launch_bounds__(256) void ln_kernel(
    const float* __restrict__ A, const float* __restrict__ R,
    const float* __restrict__ g, const float* __restrict__ bt,
    float* __restrict__ out)
{
    const int row = blockIdx.x;
    const int tid = threadIdx.x;
    float v = A[(size_t)row * DD + tid] + R[(size_t)row * DD + tid];

    __shared__ float red[256];
    red[tid] = v;
    __syncthreads();
    for (int s = 128; s > 0; s >>= 1) {
        if (tid < s) red[tid] += red[tid + s];
        __syncthreads();
    }
    float mean = red[0] * (1.f / DD);
    __syncthreads();
    float c = v - mean;
    red[tid] = c * c;
    __syncthreads();
    for (int s = 128; s > 0; s >>= 1) {
        if (tid < s) red[tid] += red[tid + s];
        __syncthreads();
    }
    float var = red[0] * (1.f / DD);
    out[(size_t)row * DD + tid] = c * rsqrtf(var + 1e-5f) * g[tid] + bt[tid];
}

// ---------------- GASA geometric bias: biasT[b][l][q] = beta*clip(...) -----
__global__ __launch_bounds__(128) void gasa_bias_kernel(
    const float* __restrict__ qpos, const float* __restrict__ mpos,
    const float* __restrict__ w1, const float* __restrict__ b1,
    const float* __restrict__ w2, const float* __restrict__ b2,
    const float* __restrict__ betap, float* __restrict__ biasT)
{
    const int b = blockIdx.z;
    const int l = blockIdx.y;
    const int q = blockIdx.x * 128 + threadIdx.x;

    __shared__ float sw1[KD], sb1[KD], sw2[KD], smp[3];
    if (threadIdx.x < KD) {
        sw1[threadIdx.x] = w1[threadIdx.x];
        sb1[threadIdx.x] = b1[threadIdx.x];
        sw2[threadIdx.x] = w2[threadIdx.x];
    }
    if (threadIdx.x < 3)
        smp[threadIdx.x] = mpos[((size_t)b * LL + l) * 3 + threadIdx.x];
    __syncthreads();

    if (q >= QQ) return;
    const float* qp = qpos + ((size_t)b * QQ + q) * 3;
    float dx = qp[0] - smp[0], dy = qp[1] - smp[1], dz = qp[2] - smp[2];
    float dist = sqrtf(fmaxf(dx * dx + dy * dy + dz * dz, 0.f));

    float s = 0.f;
    #pragma unroll
    for (int k = 0; k < KD; k++) {
        float h = fmaxf(dist * sw1[k] + sb1[k], 0.f);
        s += h * sw2[k];
    }
    s += b2[0];
    s = fminf(fmaxf(s, -10.f), 0.f);
    biasT[((size_t)b * LL + l) * QQ + q] = s * betap[0];
}

// ---------------- split-L flash attention partials ----------------
// grid: (QT*S, H, B), 128 threads; thread = one query. 8-key chunks in smem.
#define CH 8
__global__ __launch_bounds__(128) void attn_part_kernel(
    const float* __restrict__ Qp, int qstride,
    const float* __restrict__ Kp, const float* __restrict__ Vp, int kvstride,
    const float* __restrict__ biasT, int Lk, int S, int step,
    float* __restrict__ pm, float* __restrict__ pl, float* __restrict__ pacc,
    int useBias)
{
    const int b = blockIdx.z, h = blockIdx.y;
    const int sp = blockIdx.x / QT;
    const int qt = blockIdx.x % QT;
    const int tid = threadIdx.x;
    const int q = qt * 128 + tid;
    const bool active = (q < QQ);

    const int ls = sp * step;
    const int le = min(ls + step, Lk);   // (le - ls) is a multiple of 8 by construction

    u64 q2[HD / 2];
    if (active) {
        const ulonglong2* qp2 = reinterpret_cast<const ulonglong2*>(
            Qp + ((size_t)(b * QQ + q)) * qstride + h * HD);
        #pragma unroll
        for (int i = 0; i < HD / 4; i++) {
            ulonglong2 t = qp2[i];
            q2[2 * i] = t.x; q2[2 * i + 1] = t.y;
        }
    }
    u64 acc2[HD / 2];
    #pragma unroll
    for (int d = 0; d < HD / 2; d++) acc2[d] = 0ull;
    float m = -INFINITY, lsum = 0.f;

    __shared__ __align__(16) float Ks[CH][HD];
    __shared__ __align__(16) float Vs[CH][HD];

    const int lrow = tid >> 4;          // 0..7
    const int lcol = (tid & 15) * 2;    // 0..30

    for (int l0 = ls; l0 < le; l0 += CH) {
        // cooperative K/V chunk load (float2 per thread per array)
        {
            size_t row = (size_t)(b * Lk + l0 + lrow);
            const float2* kp = reinterpret_cast<const float2*>(
                Kp + row * kvstride + h * HD + lcol);
            const float2* vp = reinterpret_cast<const float2*>(
                Vp + row * kvstride + h * HD + lcol);
            *reinterpret_cast<float2*>(&Ks[lrow][lcol]) = *kp;
            *reinterpret_cast<float2*>(&Vs[lrow][lcol]) = *vp;
        }
        float bfr[CH];
        if (useBias) {
            #pragma unroll
            for (int li = 0; li < CH; li++)
                bfr[li] = active
                    ? biasT[((size_t)(b * Lk + l0 + li)) * QQ + q] : 0.f;
        }
        __syncthreads();

        if (active) {
            float s[CH];
            #pragma unroll
            for (int li = 0; li < CH; li++) {
                const u64* K2 = reinterpret_cast<const u64*>(Ks[li]);
                u64 t = 0ull;
                #pragma unroll
                for (int d = 0; d < HD / 2; d++) fma2(t, q2[d], K2[d]);
                float lo, hi; upk2(t, lo, hi);
                s[li] = (lo + hi) * SCALE;
                if (useBias) s[li] += bfr[li];
            }
            float cm = s[0];
            #pragma unroll
            for (int li = 1; li < CH; li++) cm = fmaxf(cm, s[li]);
            if (cm > m) {
                float corr = __expf(m - cm);
                m = cm;
                lsum *= corr;
                u64 c2 = pk2(corr, corr);
                #pragma unroll
                for (int d = 0; d < HD / 2; d++) mul2(acc2[d], c2);
            }
            #pragma unroll
            for (int li = 0; li < CH; li++) {
                float p = __expf(s[li] - m);
                lsum += p;
                u64 p2 = pk2(p, p);
                const u64* V2 = reinterpret_cast<const u64*>(Vs[li]);
                #pragma unroll
                for (int d = 0; d < HD / 2; d++) fma2(acc2[d], p2, V2[d]);
            }
        }
        __syncthreads();
    }

    if (active) {
        size_t pidx = (((size_t)(b * HH + h)) * S + sp) * QQ + q;
        pm[pidx] = m;
        pl[pidx] = lsum;
        u64* ap = reinterpret_cast<u64*>(pacc + pidx * HD);
        #pragma unroll
        for (int d = 0; d < HD / 2; d++) ap[d] = acc2[d];
    }
}

// ---------------- split combine: out[b][q][h*HD+d] ----------------
__global__ __launch_bounds__(128) void attn_combine_kernel(
    const float* __restrict__ pm, const float* __restrict__ pl,
    const float* __restrict__ pacc, int S, float* __restrict__ out)
{
    int t = blockIdx.x * 128 + threadIdx.x;
    if (t >= BB * HH * QQ) return;
    int q = t % QQ;
    int bh = t / QQ;
    int b = bh / HH, h = bh % HH;

    float mg = -INFINITY;
    for (int s = 0; s < S; s++)
        mg = fmaxf(mg, pm[((size_t)bh * S + s) * QQ + q]);
    float w[8], Lsum = 0.f;
    for (int s = 0; s < S; s++) {
        w[s] = __expf(pm[((size_t)bh * S + s) * QQ + q] - mg);
        Lsum += pl[((size_t)bh * S + s) * QQ + q] * w[s];
    }
    float inv = 1.f / Lsum;
    float o[HD];
    #pragma unroll
    for (int d = 0; d < HD; d++) o[d] = 0.f;
    for (int s = 0; s < S; s++) {
        float ws = w[s];
        const float* ap = pacc + (((size_t)bh * S + s) * QQ + q) * HD;
        #pragma unroll
        for (int d = 0; d < HD; d++) o[d] += ws * ap[d];
    }
    float* op = out + ((size_t)(b * QQ + q)) * DD + h * HD;
    #pragma unroll
    for (int d = 0; d < HD; d++) op[d] = o[d] * inv;
}

// ---------------- host launcher ----------------
static inline int cdiv(int a, int b) { return (a + b - 1) / b; }

extern "C" void kernel_launch(void* const* d_in, const int* in_sizes, int n_in,
                              void* d_out, int out_size)
{
    const float* queries   = (const float*)d_in[0];
    const float* memory    = (const float*)d_in[1];
    const float* memory_pos= (const float*)d_in[2];
    const float* query_pos = (const float*)d_in[3];
    const float* sa_in_w   = (const float*)d_in[4];
    const float* sa_in_b   = (const float*)d_in[5];
    const float* sa_out_w  = (const float*)d_in[6];
    const float* sa_out_b  = (const float*)d_in[7];
    const float* norm1_g   = (const float*)d_in[8];
    const float* norm1_b   = (const float*)d_in[9];
    const float* q_w       = (const float*)d_in[10];
    const float* q_b       = (const float*)d_in[11];
    const float* k_w       = (const float*)d_in[12];
    const float* k_b       = (const float*)d_in[13];
    const float* v_w       = (const float*)d_in[14];
    const float* v_b       = (const float*)d_in[15];
    const float* o_w       = (const float*)d_in[16];
    const float* o_b       = (const float*)d_in[17];
    const float* norm2_g   = (const float*)d_in[18];
    const float* norm2_b   = (const float*)d_in[19];
    const float* beta      = (const float*)d_in[20];
    const float* dk_w1     = (const float*)d_in[21];
    const float* dk_b1     = (const float*)d_in[22];
    const float* dk_w2     = (const float*)d_in[23];
    const float* dk_b2     = (const float*)d_in[24];
    const float* ffn_w1    = (const float*)d_in[25];
    const float* ffn_b1    = (const float*)d_in[26];
    const float* ffn_w2    = (const float*)d_in[27];
    const float* ffn_b2    = (const float*)d_in[28];
    const float* norm3_g   = (const float*)d_in[29];
    const float* norm3_b   = (const float*)d_in[30];

    float *g_qkv, *g_sa, *g_tmp, *g_x1, *g_x2, *g_q, *g_k, *g_v, *g_bias,
          *g_ca, *g_ffn, *g_pm, *g_pl, *g_pacc;
    cudaGetSymbolAddress((void**)&g_qkv,  s_qkv);
    cudaGetSymbolAddress((void**)&g_sa,   s_sa);
    cudaGetSymbolAddress((void**)&g_tmp,  s_tmp);
    cudaGetSymbolAddress((void**)&g_x1,   s_x1);
    cudaGetSymbolAddress((void**)&g_x2,   s_x2);
    cudaGetSymbolAddress((void**)&g_q,    s_q);
    cudaGetSymbolAddress((void**)&g_k,    s_k);
    cudaGetSymbolAddress((void**)&g_v,    s_v);
    cudaGetSymbolAddress((void**)&g_bias, s_bias);
    cudaGetSymbolAddress((void**)&g_ca,   s_ca);
    cudaGetSymbolAddress((void**)&g_ffn,  s_ffn);
    cudaGetSymbolAddress((void**)&g_pm,   s_pm);
    cudaGetSymbolAddress((void**)&g_pl,   s_pl);
    cudaGetSymbolAddress((void**)&g_pacc, s_pacc);

    const int Mq = BB * QQ;   // 2400
    const int Mm = BB * LL;   // 8192
    const int NBHQ = BB * HH * QQ;

    // 1) self-attn packed in-proj
    gemm2_kernel<<<dim3(3 * DD / GN, cdiv(Mq, GM)), 128>>>(
        queries, sa_in_w, sa_in_b, g_qkv, Mq, 3 * DD, DD, 0);

    // 5a) GASA geometric bias (independent — launch early)
    gasa_bias_kernel<<<dim3(QT, LL, BB), 128>>>(
        query_pos, memory_pos, dk_w1, dk_b1, dk_w2, dk_b2, beta, g_bias);

    // 2) self-attention (no bias), split-L S=4, step=152 (mult of 8)
    {
        int S = 4, step = cdiv(QQ, S * CH) * CH;
        attn_part_kernel<<<dim3(QT * S, HH, BB), 128>>>(
            g_qkv, 3 * DD, g_qkv + DD, g_qkv + 2 * DD, 3 * DD,
            nullptr, QQ, S, step, g_pm, g_pl, g_pacc, 0);
        attn_combine_kernel<<<cdiv(NBHQ, 128), 128>>>(g_pm, g_pl, g_pacc, S, g_sa);
    }

    // 3) SA out-proj + LN1
    gemm2_kernel<<<dim3(DD / GN, cdiv(Mq, GM)), 128>>>(
        g_sa, sa_out_w, sa_out_b, g_tmp, Mq, DD, DD, 0);
    ln_kernel<<<Mq, 256>>>(queries, g_tmp, norm1_g, norm1_b, g_x1);

    // 4) cross projections
    gemm2_kernel<<<dim3(DD / GN, cdiv(Mq, GM)), 128>>>(
        g_x1, q_w, q_b, g_q, Mq, DD, DD, 0);
    gemm2_kernel<<<dim3(DD / GN, cdiv(Mm, GM)), 128>>>(
        memory, k_w, k_b, g_k, Mm, DD, DD, 0);
    gemm2_kernel<<<dim3(DD / GN, cdiv(Mm, GM)), 128>>>(
        memory, v_w, v_b, g_v, Mm, DD, DD, 0);

    // 6) cross-attention with bias, split-L S=8, step=256
    {
        int S = 8, step = cdiv(LL, S * CH) * CH;
        attn_part_kernel<<<dim3(QT * S, HH, BB), 128>>>(
            g_q, DD, g_k, g_v, DD, g_bias, LL, S, step, g_pm, g_pl, g_pacc, 1);
        attn_combine_kernel<<<cdiv(NBHQ, 128), 128>>>(g_pm, g_pl, g_pacc, S, g_ca);
    }

    // 7) O proj + LN2
    gemm2_kernel<<<dim3(DD / GN, cdiv(Mq, GM)), 128>>>(
        g_ca, o_w, o_b, g_tmp, Mq, DD, DD, 0);
    ln_kernel<<<Mq, 256>>>(g_x1, g_tmp, norm2_g, norm2_b, g_x2);

    // 8) FFN + LN3 -> output
    gemm2_kernel<<<dim3(DFF / GN, cdiv(Mq, GM)), 128>>>(
        g_x2, ffn_w1, ffn_b1, g_ffn, Mq, DFF, DD, 1);
    gemm2_kernel<<<dim3(DD / GN, cdiv(Mq, GM)), 128>>>(
        g_ffn, ffn_w2, ffn_b2, g_tmp, Mq, DD, DFF, 0);
    ln_kernel<<<Mq, 256>>>(g_x2, g_tmp, norm3_g, norm3_b, (float*)d_out);
}

// round 3
// speedup vs baseline: 2.4979x; 1.6048x over previous
#include <cuda_runtime.h>
#include <cuda_bf16.h>
#include <math.h>
#include <stdint.h>

// ---------------- problem constants ----------------
#define BB 4
#define QQ 600
#define LL 2048
#define DD 256
#define HH 8
#define HD 32
#define DFF 2048
#define KD 32
#define SCALE 0.17677669529663687f   // 32^-0.5
#define QT 5                         // ceil(600/128) query tiles

typedef unsigned long long u64;

// ---------------- f32x2 packed-math helpers ----------------
__device__ __forceinline__ u64 pk2(float lo, float hi) {
    u64 r; asm("mov.b64 %0, {%1, %2};" : "=l"(r) : "f"(lo), "f"(hi)); return r;
}
__device__ __forceinline__ void upk2(u64 v, float& lo, float& hi) {
    asm("mov.b64 {%0, %1}, %2;" : "=f"(lo), "=f"(hi) : "l"(v));
}
__device__ __forceinline__ void fma2(u64& d, u64 a, u64 b) {
    asm("fma.rn.f32x2 %0, %1, %2, %0;" : "+l"(d) : "l"(a), "l"(b));
}
__device__ __forceinline__ void mul2(u64& d, u64 a) {
    asm("mul.rn.f32x2 %0, %0, %1;" : "+l"(d) : "l"(a));
}
__device__ __forceinline__ uint32_t f2tf32(float x) {
    uint32_t u; asm("cvt.rna.tf32.f32 %0, %1;" : "=r"(u) : "f"(x)); return u;
}
__device__ __forceinline__ void mma8(float c[4], uint32_t a0, uint32_t a1,
                                     uint32_t a2, uint32_t a3,
                                     uint32_t b0, uint32_t b1) {
    asm("mma.sync.aligned.m16n8k8.row.col.f32.tf32.tf32.f32 "
        "{%0,%1,%2,%3},{%4,%5,%6,%7},{%8,%9},{%0,%1,%2,%3};"
        : "+f"(c[0]), "+f"(c[1]), "+f"(c[2]), "+f"(c[3])
        : "r"(a0), "r"(a1), "r"(a2), "r"(a3), "r"(b0), "r"(b1));
}

// ---------------- scratch (device globals) ----------------
__device__ float s_qkv [BB*QQ*3*DD];
__device__ float s_sa  [BB*QQ*DD];
__device__ float s_tmp [BB*QQ*DD];
__device__ float s_x1  [BB*QQ*DD];
__device__ float s_x2  [BB*QQ*DD];
__device__ float s_q   [BB*QQ*DD];
__device__ float s_k   [BB*LL*DD];
__device__ float s_v   [BB*LL*DD];
__device__ float s_bias[BB*LL*QQ];           // beta * clipped bias, [B, L, Q]
__device__ float s_ca  [BB*QQ*DD];
__device__ float s_ffn [BB*QQ*DFF];
__device__ float s_part[4*BB*QQ*DD];         // ffn2 split-K partials
__device__ float s_pm  [BB*HH*8*QQ];
__device__ float s_pl  [BB*HH*8*QQ];
__device__ float s_pacc[BB*HH*8*QQ*HD];

// ---------------- TF32 tensor-core GEMM ----------------
// C[M,N] = A[M,K] @ W[N,K]^T (+bias, opt relu). 256 threads, 8 warps (4m x 2n).
// MF = m-frags per warp (1 -> BM=64, 2 -> BM=128). grid.z = split-K count:
// if >1, each z writes a bias-free partial at C + z*M*N.
#define KPAD 20

template<int MF>
__global__ __launch_bounds__(256) void gemm_tf32_kernel(
    const float* __restrict__ A, const float* __restrict__ W,
    const float* __restrict__ bias, float* __restrict__ C,
    int M, int N, int K, int relu)
{
    const int BM = 64 * MF;
    __shared__ __align__(16) uint32_t As[128][KPAD];   // [m][k], rows 0..BM-1 used
    __shared__ __align__(16) uint32_t Ws[64][KPAD];    // [n][k]

    const int tid = threadIdx.x;
    const int lane = tid & 31;
    const int w = tid >> 5;            // 0..7
    const int wm = w & 3;              // 4 m-warps
    const int wn = w >> 2;             // 2 n-warps
    const int g = lane >> 2;           // 0..7
    const int t = lane & 3;            // 0..3

    const int m0 = blockIdx.y * BM;
    const int n0 = blockIdx.x * 64;

    const int nsplit = gridDim.z;
    const int Klen = K / nsplit;
    const int kstart = blockIdx.z * Klen;
    float* Cout = (nsplit > 1) ? (C + (size_t)blockIdx.z * M * N) : C;

    const int lr = tid >> 2;           // 0..63
    const int kc = (tid & 3) * 4;      // 0,4,8,12

    float acc[MF][4][4];
    #pragma unroll
    for (int i = 0; i < MF; i++)
        #pragma unroll
        for (int j = 0; j < 4; j++)
            #pragma unroll
            for (int e = 0; e < 4; e++) acc[i][j][e] = 0.f;

    const int m_warp = wm * (16 * MF);
    const int n_warp = wn * 32;

    for (int it = 0; it < Klen / 16; it++) {
        const int kg = kstart + it * 16 + kc;
        // A tile -> As[m][k] (tf32-converted), STS.128
        #pragma unroll
        for (int half = 0; half < MF; half++) {
            int r = lr + half * 64;
            int arow = m0 + r;
            float4 av = make_float4(0.f, 0.f, 0.f, 0.f);
            if (arow < M)
                av = *reinterpret_cast<const float4*>(A + (size_t)arow * K + kg);
            uint4 u = make_uint4(f2tf32(av.x), f2tf32(av.y), f2tf32(av.z), f2tf32(av.w));
            *reinterpret_cast<uint4*>(&As[r][kc]) = u;
        }
        // W tile -> Ws[n][k]
        {
            float4 wv = *reinterpret_cast<const float4*>(W + (size_t)(n0 + lr) * K + kg);
            uint4 u = make_uint4(f2tf32(wv.x), f2tf32(wv.y), f2tf32(wv.z), f2tf32(wv.w));
            *reinterpret_cast<uint4*>(&Ws[lr][kc]) = u;
        }
        __syncthreads();

        #pragma unroll
        for (int kk = 0; kk < 16; kk += 8) {
            uint32_t b0[4], b1[4];
            #pragma unroll
            for (int ni = 0; ni < 4; ni++) {
                b0[ni] = Ws[n_warp + ni * 8 + g][kk + t];
                b1[ni] = Ws[n_warp + ni * 8 + g][kk + t + 4];
            }
            #pragma unroll
            for (int mi = 0; mi < MF; mi++) {
                int mb = m_warp + mi * 16;
                uint32_t a0 = As[mb + g][kk + t];
                uint32_t a1 = As[mb + g + 8][kk + t];
                uint32_t a2 = As[mb + g][kk + t + 4];
                uint32_t a3 = As[mb + g + 8][kk + t + 4];
                #pragma unroll
                for (int ni = 0; ni < 4; ni++)
                    mma8(acc[mi][ni], a0, a1, a2, a3, b0[ni], b1[ni]);
            }
        }
        __syncthreads();
    }

    // epilogue
    #pragma unroll
    for (int mi = 0; mi < MF; mi++) {
        #pragma unroll
        for (int ni = 0; ni < 4; ni++) {
            int col = n0 + n_warp + ni * 8 + 2 * t;
            float bz0 = 0.f, bz1 = 0.f;
            if (nsplit == 1) { bz0 = bias[col]; bz1 = bias[col + 1]; }
            int r0 = m0 + m_warp + mi * 16 + g;
            int r1 = r0 + 8;
            float v0 = acc[mi][ni][0] + bz0, v1 = acc[mi][ni][1] + bz1;
            float v2 = acc[mi][ni][2] + bz0, v3 = acc[mi][ni][3] + bz1;
            if (relu) {
                v0 = fmaxf(v0, 0.f); v1 = fmaxf(v1, 0.f);
                v2 = fmaxf(v2, 0.f); v3 = fmaxf(v3, 0.f);
            }
            if (r0 < M) *reinterpret_cast<float2*>(Cout + (size_t)r0 * N + col) = make_float2(v0, v1);
            if (r1 < M) *reinterpret_cast<float2*>(Cout + (size_t)r1 * N + col) = make_float2(v2, v3);
        }
    }
}

// ---------------- LayerNorm helpers ----------------
__device__ __forceinline__ void ln_core(float v, int tid, const float* g,
                                        const float* bt, float* out, size_t row)
{
    float s1 = v, s2 = v * v;
    #pragma unroll
    for (int o = 16; o > 0; o >>= 1) {
        s1 += __shfl_xor_sync(0xffffffffu, s1, o);
        s2 += __shfl_xor_sync(0xffffffffu, s2, o);
    }
    __shared__ float r1[8], r2[8];
    int wid = tid >> 5, lane = tid & 31;
    if (lane == 0) { r1[wid] = s1; r2[wid] = s2; }
    __syncthreads();
    if (tid < 32) {
        float a = (lane < 8) ? r1[lane] : 0.f;
        float b = (lane < 8) ? r2[lane] : 0.f;
        #pragma unroll
        for (int o = 4; o > 0; o >>= 1) {
            a += __shfl_xor_sync(0xffffffffu, a, o);
            b += __shfl_xor_sync(0xffffffffu, b, o);
        }
        if (lane == 0) { r1[0] = a; r2[0] = b; }
    }
    __syncthreads();
    float mean = r1[0] * (1.f / DD);
    float var = r2[0] * (1.f / DD) - mean * mean;
    out[row * DD + tid] = (v - mean) * rsqrtf(var + 1e-5f) * g[tid] + bt[tid];
}

__global__ __launch_bounds__(256) void ln_kernel(
    const float* __restrict__ A, const float* __restrict__ R,
    const float* __restrict__ g, const float* __restrict__ bt,
    float* __restrict__ out)
{
    const size_t row = blockIdx.x;
    const int tid = threadIdx.x;
    float v = A[row * DD + tid] + R[row * DD + tid];
    ln_core(v, tid, g, bt, out, row);
}

// LN3 with ffn2 split-K combine: out = LN(x + (sum parts + fbias))
__global__ __launch_bounds__(256) void ln_split_kernel(
    const float* __restrict__ X, const float* __restrict__ parts,
    const float* __restrict__ fbias,
    const float* __restrict__ g, const float* __restrict__ bt,
    float* __restrict__ out, int nsplit)
{
    const size_t row = blockIdx.x;
    const int tid = threadIdx.x;
    const size_t stride = (size_t)BB * QQ * DD;
    float f = fbias[tid];
    for (int s = 0; s < nsplit; s++) f += parts[s * stride + row * DD + tid];
    float v = X[row * DD + tid] + f;
    ln_core(v, tid, g, bt, out, row);
}

// ---------------- GASA geometric bias: biasT[b][l][q] = beta*clip(...) -----
__global__ __launch_bounds__(128) void gasa_bias_kernel(
    const float* __restrict__ qpos, const float* __restrict__ mpos,
    const float* __restrict__ w1, const float* __restrict__ b1,
    const float* __restrict__ w2, const float* __restrict__ b2,
    const float* __restrict__ betap, float* __restrict__ biasT)
{
    const int b = blockIdx.z;
    const int l = blockIdx.y;
    const int q = blockIdx.x * 128 + threadIdx.x;

    __shared__ float sw1[KD], sb1[KD], sw2[KD], smp[3];
    if (threadIdx.x < KD) {
        sw1[threadIdx.x] = w1[threadIdx.x];
        sb1[threadIdx.x] = b1[threadIdx.x];
        sw2[threadIdx.x] = w2[threadIdx.x];
    }
    if (threadIdx.x < 3)
        smp[threadIdx.x] = mpos[((size_t)b * LL + l) * 3 + threadIdx.x];
    __syncthreads();

    if (q >= QQ) return;
    const float* qp = qpos + ((size_t)b * QQ + q) * 3;
    float dx = qp[0] - smp[0], dy = qp[1] - smp[1], dz = qp[2] - smp[2];
    float dist = sqrtf(fmaxf(dx * dx + dy * dy + dz * dz, 0.f));

    float s = 0.f;
    #pragma unroll
    for (int k = 0; k < KD; k++) {
        float h = fmaxf(dist * sw1[k] + sb1[k], 0.f);
        s += h * sw2[k];
    }
    s += b2[0];
    s = fminf(fmaxf(s, -10.f), 0.f);
    biasT[((size_t)b * LL + l) * QQ + q] = s * betap[0];
}

// ---------------- split-L flash attention partials ----------------
#define CH 16
__global__ __launch_bounds__(128) void attn_part_kernel(
    const float* __restrict__ Qp, int qstride,
    const float* __restrict__ Kp, const float* __restrict__ Vp, int kvstride,
    const float* __restrict__ biasT, int Lk, int S, int step,
    float* __restrict__ pm, float* __restrict__ pl, float* __restrict__ pacc,
    int useBias)
{
    const int b = blockIdx.z, h = blockIdx.y;
    const int sp = blockIdx.x / QT;
    const int qt = blockIdx.x % QT;
    const int tid = threadIdx.x;
    const int q = qt * 128 + tid;
    const bool active = (q < QQ);

    const int ls = sp * step;
    const int le = min(ls + step, Lk);

    u64 q2[HD / 2];
    if (active) {
        const ulonglong2* qp2 = reinterpret_cast<const ulonglong2*>(
            Qp + ((size_t)(b * QQ + q)) * qstride + h * HD);
        #pragma unroll
        for (int i = 0; i < HD / 4; i++) {
            ulonglong2 tv = qp2[i];
            q2[2 * i] = tv.x; q2[2 * i + 1] = tv.y;
        }
    }
    u64 acc2[HD / 2];
    #pragma unroll
    for (int d = 0; d < HD / 2; d++) acc2[d] = 0ull;
    float m = -INFINITY, lsum = 0.f;

    __shared__ __align__(16) float Ks[CH][HD];
    __shared__ __align__(16) float Vs[CH][HD];

    const int lrow = tid >> 3;          // 0..15
    const int lcol = (tid & 7) * 4;     // 0..28

    for (int l0 = ls; l0 < le; l0 += CH) {
        {
            int gr = min(b * Lk + l0 + lrow, BB * Lk - 1);
            const float4* kp = reinterpret_cast<const float4*>(
                Kp + (size_t)gr * kvstride + h * HD + lcol);
            const float4* vp = reinterpret_cast<const float4*>(
                Vp + (size_t)gr * kvstride + h * HD + lcol);
            *reinterpret_cast<float4*>(&Ks[lrow][lcol]) = *kp;
            *reinterpret_cast<float4*>(&Vs[lrow][lcol]) = *vp;
        }
        float bfr[CH];
        if (useBias) {
            #pragma unroll
            for (int li = 0; li < CH; li++)
                bfr[li] = active
                    ? biasT[((size_t)(b * Lk + l0 + li)) * QQ + q] : 0.f;
        }
        __syncthreads();

        if (active) {
            float s[CH];
            #pragma unroll
            for (int li = 0; li < CH; li++) {
                const ulonglong2* K4 = reinterpret_cast<const ulonglong2*>(Ks[li]);
                u64 tacc = 0ull;
                #pragma unroll
                for (int i = 0; i < HD / 4; i++) {
                    ulonglong2 kv = K4[i];
                    fma2(tacc, q2[2 * i], kv.x);
                    fma2(tacc, q2[2 * i + 1], kv.y);
                }
                float lo, hi; upk2(tacc, lo, hi);
                float sc = (lo + hi) * SCALE;
                if (useBias) sc += bfr[li];
                if (l0 + li >= le) sc = -1e30f;
                s[li] = sc;
            }
            float cm = s[0];
            #pragma unroll
            for (int li = 1; li < CH; li++) cm = fmaxf(cm, s[li]);
            if (cm > m) {
                float corr = __expf(m - cm);
                m = cm;
                lsum *= corr;
                u64 c2 = pk2(corr, corr);
                #pragma unroll
                for (int d = 0; d < HD / 2; d++) mul2(acc2[d], c2);
            }
            #pragma unroll
            for (int li = 0; li < CH; li++) {
                float p = __expf(s[li] - m);
                lsum += p;
                u64 p2 = pk2(p, p);
                const ulonglong2* V4 = reinterpret_cast<const ulonglong2*>(Vs[li]);
                #pragma unroll
                for (int i = 0; i < HD / 4; i++) {
                    ulonglong2 vv = V4[i];
                    fma2(acc2[2 * i], p2, vv.x);
                    fma2(acc2[2 * i + 1], p2, vv.y);
                }
            }
        }
        __syncthreads();
    }

    if (active) {
        size_t pidx = (((size_t)(b * HH + h)) * S + sp) * QQ + q;
        pm[pidx] = m;
        pl[pidx] = lsum;
        u64* ap = reinterpret_cast<u64*>(pacc + pidx * HD);
        #pragma unroll
        for (int d = 0; d < HD / 2; d++) ap[d] = acc2[d];
    }
}

// ---------------- split combine (parallel over d-pairs) ----------------
__global__ __launch_bounds__(256) void attn_combine_kernel(
    const float* __restrict__ pm, const float* __restrict__ pl,
    const float* __restrict__ pacc, int S, float* __restrict__ out)
{
    int t = blockIdx.x * 256 + threadIdx.x;
    if (t >= BB * HH * QQ * (HD / 2)) return;
    int dp = t & (HD / 2 - 1);
    int idx = t >> 4;                  // bh*QQ + q index space
    int q = idx % QQ;
    int bh = idx / QQ;
    int b = bh / HH, h = bh % HH;

    float mg = -INFINITY;
    for (int s = 0; s < S; s++)
        mg = fmaxf(mg, pm[((size_t)bh * S + s) * QQ + q]);
    float Lsum = 0.f;
    u64 o = 0ull;
    const u64* base = reinterpret_cast<const u64*>(pacc);
    for (int s = 0; s < S; s++) {
        size_t pidx = ((size_t)bh * S + s) * QQ + q;
        float w = __expf(pm[pidx] - mg);
        Lsum += pl[pidx] * w;
        u64 a = base[pidx * (HD / 2) + dp];
        fma2(o, pk2(w, w), a);
    }
    float inv = 1.f / Lsum;
    float lo, hi; upk2(o, lo, hi);
    float2* op = reinterpret_cast<float2*>(
        out + ((size_t)(b * QQ + q)) * DD + h * HD + 2 * dp);
    *op = make_float2(lo * inv, hi * inv);
}

// ---------------- host launcher ----------------
static inline int cdiv(int a, int b) { return (a + b - 1) / b; }

extern "C" void kernel_launch(void* const* d_in, const int* in_sizes, int n_in,
                              void* d_out, int out_size)
{
    const float* queries   = (const float*)d_in[0];
    const float* memory    = (const float*)d_in[1];
    const float* memory_pos= (const float*)d_in[2];
    const float* query_pos = (const float*)d_in[3];
    const float* sa_in_w   = (const float*)d_in[4];
    const float* sa_in_b   = (const float*)d_in[5];
    const float* sa_out_w  = (const float*)d_in[6];
    const float* sa_out_b  = (const float*)d_in[7];
    const float* norm1_g   = (const float*)d_in[8];
    const float* norm1_b   = (const float*)d_in[9];
    const float* q_w       = (const float*)d_in[10];
    const float* q_b       = (const float*)d_in[11];
    const float* k_w       = (const float*)d_in[12];
    const float* k_b       = (const float*)d_in[13];
    const float* v_w       = (const float*)d_in[14];
    const float* v_b       = (const float*)d_in[15];
    const float* o_w       = (const float*)d_in[16];
    const float* o_b       = (const float*)d_in[17];
    const float* norm2_g   = (const float*)d_in[18];
    const float* norm2_b   = (const float*)d_in[19];
    const float* beta      = (const float*)d_in[20];
    const float* dk_w1     = (const float*)d_in[21];
    const float* dk_b1     = (const float*)d_in[22];
    const float* dk_w2     = (const float*)d_in[23];
    const float* dk_b2     = (const float*)d_in[24];
    const float* ffn_w1    = (const float*)d_in[25];
    const float* ffn_b1    = (const float*)d_in[26];
    const float* ffn_w2    = (const float*)d_in[27];
    const float* ffn_b2    = (const float*)d_in[28];
    const float* norm3_g   = (const float*)d_in[29];
    const float* norm3_b   = (const float*)d_in[30];

    float *g_qkv, *g_sa, *g_tmp, *g_x1, *g_x2, *g_q, *g_k, *g_v, *g_bias,
          *g_ca, *g_ffn, *g_part, *g_pm, *g_pl, *g_pacc;
    cudaGetSymbolAddress((void**)&g_qkv,  s_qkv);
    cudaGetSymbolAddress((void**)&g_sa,   s_sa);
    cudaGetSymbolAddress((void**)&g_tmp,  s_tmp);
    cudaGetSymbolAddress((void**)&g_x1,   s_x1);
    cudaGetSymbolAddress((void**)&g_x2,   s_x2);
    cudaGetSymbolAddress((void**)&g_q,    s_q);
    cudaGetSymbolAddress((void**)&g_k,    s_k);
    cudaGetSymbolAddress((void**)&g_v,    s_v);
    cudaGetSymbolAddress((void**)&g_bias, s_bias);
    cudaGetSymbolAddress((void**)&g_ca,   s_ca);
    cudaGetSymbolAddress((void**)&g_ffn,  s_ffn);
    cudaGetSymbolAddress((void**)&g_part, s_part);
    cudaGetSymbolAddress((void**)&g_pm,   s_pm);
    cudaGetSymbolAddress((void**)&g_pl,   s_pl);
    cudaGetSymbolAddress((void**)&g_pacc, s_pacc);

    const int Mq = BB * QQ;   // 2400
    const int Mm = BB * LL;   // 8192
    const int NCOMB = BB * HH * QQ * (HD / 2);

    // 1) self-attn packed in-proj [2400,768]
    gemm_tf32_kernel<2><<<dim3(3 * DD / 64, cdiv(Mq, 128), 1), 256>>>(
        queries, sa_in_w, sa_in_b, g_qkv, Mq, 3 * DD, DD, 0);

    // GASA geometric bias (independent — launch early)
    gasa_bias_kernel<<<dim3(QT, LL, BB), 128>>>(
        query_pos, memory_pos, dk_w1, dk_b1, dk_w2, dk_b2, beta, g_bias);

    // 2) self-attention (no bias), split-L S=4
    {
        int S = 4, step = cdiv(QQ, S * CH) * CH;   // 160
        attn_part_kernel<<<dim3(QT * S, HH, BB), 128>>>(
            g_qkv, 3 * DD, g_qkv + DD, g_qkv + 2 * DD, 3 * DD,
            nullptr, QQ, S, step, g_pm, g_pl, g_pacc, 0);
        attn_combine_kernel<<<cdiv(NCOMB, 256), 256>>>(g_pm, g_pl, g_pacc, S, g_sa);
    }

    // 3) SA out-proj + LN1
    gemm_tf32_kernel<1><<<dim3(DD / 64, cdiv(Mq, 64), 1), 256>>>(
        g_sa, sa_out_w, sa_out_b, g_tmp, Mq, DD, DD, 0);
    ln_kernel<<<Mq, 256>>>(queries, g_tmp, norm1_g, norm1_b, g_x1);

    // 4) cross projections
    gemm_tf32_kernel<1><<<dim3(DD / 64, cdiv(Mq, 64), 1), 256>>>(
        g_x1, q_w, q_b, g_q, Mq, DD, DD, 0);
    gemm_tf32_kernel<2><<<dim3(DD / 64, cdiv(Mm, 128), 1), 256>>>(
        memory, k_w, k_b, g_k, Mm, DD, DD, 0);
    gemm_tf32_kernel<2><<<dim3(DD / 64, cdiv(Mm, 128), 1), 256>>>(
        memory, v_w, v_b, g_v, Mm, DD, DD, 0);

    // 5) cross-attention with bias, split-L S=8 (step 256)
    {
        int S = 8, step = cdiv(LL, S * CH) * CH;
        attn_part_kernel<<<dim3(QT * S, HH, BB), 128>>>(
            g_q, DD, g_k, g_v, DD, g_bias, LL, S, step, g_pm, g_pl, g_pacc, 1);
        attn_combine_kernel<<<cdiv(NCOMB, 256), 256>>>(g_pm, g_pl, g_pacc, S, g_ca);
    }

    // 6) O proj + LN2
    gemm_tf32_kernel<1><<<dim3(DD / 64, cdiv(Mq, 64), 1), 256>>>(
        g_ca, o_w, o_b, g_tmp, Mq, DD, DD, 0);
    ln_kernel<<<Mq, 256>>>(g_x1, g_tmp, norm2_g, norm2_b, g_x2);

    // 7) FFN1 (relu)
    gemm_tf32_kernel<2><<<dim3(DFF / 64, cdiv(Mq, 128), 1), 256>>>(
        g_x2, ffn_w1, ffn_b1, g_ffn, Mq, DFF, DD, 1);

    // 8) FFN2 split-K=4 partials + fused combine in LN3 -> output
    gemm_tf32_kernel<1><<<dim3(DD / 64, cdiv(Mq, 64), 4), 256>>>(
        g_ffn, ffn_w2, ffn_b2, g_part, Mq, DD, DFF, 0);
    ln_split_kernel<<<Mq, 256>>>(g_x2, g_part, ffn_b2, norm3_g, norm3_b,
                                 (float*)d_out, 4);
}

// round 4
// speedup vs baseline: 2.6942x; 1.0786x over previous
#include <cuda_runtime.h>
#include <cuda_bf16.h>
#include <math.h>
#include <stdint.h>

// ---------------- problem constants ----------------
#define BB 4
#define QQ 600
#define LL 2048
#define DD 256
#define HH 8
#define HD 32
#define DFF 2048
#define KD 32
#define SCALE 0.17677669529663687f   // 32^-0.5
#define QT 5                         // ceil(600/128) query tiles

typedef unsigned long long u64;

// ---------------- f32x2 packed-math helpers ----------------
__device__ __forceinline__ u64 pk2(float lo, float hi) {
    u64 r; asm("mov.b64 %0, {%1, %2};" : "=l"(r) : "f"(lo), "f"(hi)); return r;
}
__device__ __forceinline__ void upk2(u64 v, float& lo, float& hi) {
    asm("mov.b64 {%0, %1}, %2;" : "=f"(lo), "=f"(hi) : "l"(v));
}
__device__ __forceinline__ void fma2(u64& d, u64 a, u64 b) {
    asm("fma.rn.f32x2 %0, %1, %2, %0;" : "+l"(d) : "l"(a), "l"(b));
}
__device__ __forceinline__ void mul2(u64& d, u64 a) {
    asm("mul.rn.f32x2 %0, %0, %1;" : "+l"(d) : "l"(a));
}
__device__ __forceinline__ void mma8(float c[4], uint32_t a0, uint32_t a1,
                                     uint32_t a2, uint32_t a3,
                                     uint32_t b0, uint32_t b1) {
    asm("mma.sync.aligned.m16n8k8.row.col.f32.tf32.tf32.f32 "
        "{%0,%1,%2,%3},{%4,%5,%6,%7},{%8,%9},{%0,%1,%2,%3};"
        : "+f"(c[0]), "+f"(c[1]), "+f"(c[2]), "+f"(c[3])
        : "r"(a0), "r"(a1), "r"(a2), "r"(a3), "r"(b0), "r"(b1));
}
__device__ __forceinline__ void cp16(uint32_t dst, const void* src, int srcsize) {
    asm volatile("cp.async.ca.shared.global [%0], [%1], 16, %2;"
                 :: "r"(dst), "l"(src), "r"(srcsize));
}
__device__ __forceinline__ void cp_commit() {
    asm volatile("cp.async.commit_group;");
}
__device__ __forceinline__ void cp_wait1() {
    asm volatile("cp.async.wait_group 1;");
}

// ---------------- scratch (device globals) ----------------
__device__ float s_qkv [BB*QQ*3*DD];
__device__ float s_sa  [BB*QQ*DD];
__device__ float s_tmp [BB*QQ*DD];
__device__ float s_x1  [BB*QQ*DD];
__device__ float s_x2  [BB*QQ*DD];
__device__ float s_q   [BB*QQ*DD];
__device__ float s_k   [BB*LL*DD];
__device__ float s_v   [BB*LL*DD];
__device__ float s_bias[BB*LL*QQ];           // beta * clipped bias, [B, L, Q]
__device__ float s_ca  [BB*QQ*DD];
__device__ float s_ffn [BB*QQ*DFF];
__device__ float s_part[4*BB*QQ*DD];         // ffn2 split-K partials
__device__ float s_pm  [BB*HH*8*QQ];
__device__ float s_pl  [BB*HH*8*QQ];
__device__ float s_pacc[BB*HH*8*QQ*HD];

// ---------------- TF32 tensor-core GEMM (cp.async double-buffered) --------
// C[M,N] = A[M,K] @ W[N,K]^T (+bias, opt relu). 256 threads, 8 warps (4m x 2n).
// MF = m-frags per warp (1 -> BM=64, 2 -> BM=128). grid.z = split-K count:
// if >1, each z writes a bias-free partial at C + z*M*N.
// fp32 bits are fed directly to mma.tf32 (HW truncates mantissa).
#define KPAD 20

template<int MF>
__global__ __launch_bounds__(256) void gemm_tf32_kernel(
    const float* __restrict__ A, const float* __restrict__ W,
    const float* __restrict__ bias, float* __restrict__ C,
    int M, int N, int K, int relu)
{
    __shared__ __align__(16) uint32_t As[2][64 * MF][KPAD];
    __shared__ __align__(16) uint32_t Ws[2][64][KPAD];

    const int tid = threadIdx.x;
    const int lane = tid & 31;
    const int w = tid >> 5;            // 0..7
    const int wm = w & 3;              // 4 m-warps
    const int wn = w >> 2;             // 2 n-warps
    const int g = lane >> 2;           // 0..7
    const int t = lane & 3;            // 0..3

    const int m0 = blockIdx.y * (64 * MF);
    const int n0 = blockIdx.x * 64;

    const int nsplit = gridDim.z;
    const int Klen = K / nsplit;
    const int kstart = blockIdx.z * Klen;
    float* Cout = (nsplit > 1) ? (C + (size_t)blockIdx.z * M * N) : C;

    const int lr = tid >> 2;           // 0..63
    const int kc = (tid & 3) * 4;      // 0,4,8,12

    const uint32_t as_base = (uint32_t)__cvta_generic_to_shared(&As[0][0][0]);
    const uint32_t ws_base = (uint32_t)__cvta_generic_to_shared(&Ws[0][0][0]);

    float acc[MF][4][4];
    #pragma unroll
    for (int i = 0; i < MF; i++)
        #pragma unroll
        for (int j = 0; j < 4; j++)
            #pragma unroll
            for (int e = 0; e < 4; e++) acc[i][j][e] = 0.f;

    const int m_warp = wm * (16 * MF);
    const int n_warp = wn * 32;
    const int nIter = Klen / 16;

    // stage loader: cp.async 16B per op, zero-fill for OOB A rows
    auto load_stage = [&](int st, int it) {
        const int kg = kstart + it * 16 + kc;
        #pragma unroll
        for (int half = 0; half < MF; half++) {
            int r = lr + half * 64;
            int arow = m0 + r;
            uint32_t dst = as_base + ((st * (64 * MF) + r) * KPAD + kc) * 4;
            const float* src = A + (size_t)arow * K + kg;
            cp16(dst, src, (arow < M) ? 16 : 0);
        }
        {
            uint32_t dst = ws_base + ((st * 64 + lr) * KPAD + kc) * 4;
            const float* src = W + (size_t)(n0 + lr) * K + kg;
            cp16(dst, src, 16);
        }
        cp_commit();
    };

    load_stage(0, 0);

    for (int it = 0; it < nIter; it++) {
        if (it + 1 < nIter) load_stage((it + 1) & 1, it + 1);
        else cp_commit();               // empty group keeps wait count aligned
        cp_wait1();
        __syncthreads();

        const int st = it & 1;
        #pragma unroll
        for (int kk = 0; kk < 16; kk += 8) {
            uint32_t b0[4], b1[4];
            #pragma unroll
            for (int ni = 0; ni < 4; ni++) {
                b0[ni] = Ws[st][n_warp + ni * 8 + g][kk + t];
                b1[ni] = Ws[st][n_warp + ni * 8 + g][kk + t + 4];
            }
            #pragma unroll
            for (int mi = 0; mi < MF; mi++) {
                int mb = m_warp + mi * 16;
                uint32_t a0 = As[st][mb + g][kk + t];
                uint32_t a1 = As[st][mb + g + 8][kk + t];
                uint32_t a2 = As[st][mb + g][kk + t + 4];
                uint32_t a3 = As[st][mb + g + 8][kk + t + 4];
                #pragma unroll
                for (int ni = 0; ni < 4; ni++)
                    mma8(acc[mi][ni], a0, a1, a2, a3, b0[ni], b1[ni]);
            }
        }
        __syncthreads();
    }

    // epilogue
    #pragma unroll
    for (int mi = 0; mi < MF; mi++) {
        #pragma unroll
        for (int ni = 0; ni < 4; ni++) {
            int col = n0 + n_warp + ni * 8 + 2 * t;
            float bz0 = 0.f, bz1 = 0.f;
            if (nsplit == 1) { bz0 = bias[col]; bz1 = bias[col + 1]; }
            int r0 = m0 + m_warp + mi * 16 + g;
            int r1 = r0 + 8;
            float v0 = acc[mi][ni][0] + bz0, v1 = acc[mi][ni][1] + bz1;
            float v2 = acc[mi][ni][2] + bz0, v3 = acc[mi][ni][3] + bz1;
            if (relu) {
                v0 = fmaxf(v0, 0.f); v1 = fmaxf(v1, 0.f);
                v2 = fmaxf(v2, 0.f); v3 = fmaxf(v3, 0.f);
            }
            if (r0 < M) *reinterpret_cast<float2*>(Cout + (size_t)r0 * N + col) = make_float2(v0, v1);
            if (r1 < M) *reinterpret_cast<float2*>(Cout + (size_t)r1 * N + col) = make_float2(v2, v3);
        }
    }
}

// ---------------- LayerNorm helpers ----------------
__device__ __forceinline__ void ln_core(float v, int tid, const float* g,
                                        const float* bt, float* out, size_t row)
{
    float s1 = v, s2 = v * v;
    #pragma unroll
    for (int o = 16; o > 0; o >>= 1) {
        s1 += __shfl_xor_sync(0xffffffffu, s1, o);
        s2 += __shfl_xor_sync(0xffffffffu, s2, o);
    }
    __shared__ float r1[8], r2[8];
    int wid = tid >> 5, lane = tid & 31;
    if (lane == 0) { r1[wid] = s1; r2[wid] = s2; }
    __syncthreads();
    if (tid < 32) {
        float a = (lane < 8) ? r1[lane] : 0.f;
        float b = (lane < 8) ? r2[lane] : 0.f;
        #pragma unroll
        for (int o = 4; o > 0; o >>= 1) {
            a += __shfl_xor_sync(0xffffffffu, a, o);
            b += __shfl_xor_sync(0xffffffffu, b, o);
        }
        if (lane == 0) { r1[0] = a; r2[0] = b; }
    }
    __syncthreads();
    float mean = r1[0] * (1.f / DD);
    float var = r2[0] * (1.f / DD) - mean * mean;
    out[row * DD + tid] = (v - mean) * rsqrtf(var + 1e-5f) * g[tid] + bt[tid];
}

__global__ __launch_bounds__(256) void ln_kernel(
    const float* __restrict__ A, const float* __restrict__ R,
    const float* __restrict__ g, const float* __restrict__ bt,
    float* __restrict__ out)
{
    const size_t row = blockIdx.x;
    const int tid = threadIdx.x;
    float v = A[row * DD + tid] + R[row * DD + tid];
    ln_core(v, tid, g, bt, out, row);
}

// LN3 with ffn2 split-K combine: out = LN(x + (sum parts + fbias))
__global__ __launch_bounds__(256) void ln_split_kernel(
    const float* __restrict__ X, const float* __restrict__ parts,
    const float* __restrict__ fbias,
    const float* __restrict__ g, const float* __restrict__ bt,
    float* __restrict__ out, int nsplit)
{
    const size_t row = blockIdx.x;
    const int tid = threadIdx.x;
    const size_t stride = (size_t)BB * QQ * DD;
    float f = fbias[tid];
    for (int s = 0; s < nsplit; s++) f += parts[s * stride + row * DD + tid];
    float v = X[row * DD + tid] + f;
    ln_core(v, tid, g, bt, out, row);
}

// ---------------- GASA geometric bias: biasT[b][l][q] = beta*clip(...) -----
__global__ __launch_bounds__(128) void gasa_bias_kernel(
    const float* __restrict__ qpos, const float* __restrict__ mpos,
    const float* __restrict__ w1, const float* __restrict__ b1,
    const float* __restrict__ w2, const float* __restrict__ b2,
    const float* __restrict__ betap, float* __restrict__ biasT)
{
    const int b = blockIdx.z;
    const int l = blockIdx.y;
    const int q = blockIdx.x * 128 + threadIdx.x;

    __shared__ float sw1[KD], sb1[KD], sw2[KD], smp[3];
    if (threadIdx.x < KD) {
        sw1[threadIdx.x] = w1[threadIdx.x];
        sb1[threadIdx.x] = b1[threadIdx.x];
        sw2[threadIdx.x] = w2[threadIdx.x];
    }
    if (threadIdx.x < 3)
        smp[threadIdx.x] = mpos[((size_t)b * LL + l) * 3 + threadIdx.x];
    __syncthreads();

    if (q >= QQ) return;
    const float* qp = qpos + ((size_t)b * QQ + q) * 3;
    float dx = qp[0] - smp[0], dy = qp[1] - smp[1], dz = qp[2] - smp[2];
    float dist = sqrtf(fmaxf(dx * dx + dy * dy + dz * dz, 0.f));

    float s = 0.f;
    #pragma unroll
    for (int k = 0; k < KD; k++) {
        float h = fmaxf(dist * sw1[k] + sb1[k], 0.f);
        s += h * sw2[k];
    }
    s += b2[0];
    s = fminf(fmaxf(s, -10.f), 0.f);
    biasT[((size_t)b * LL + l) * QQ + q] = s * betap[0];
}

// ---------------- split-L flash attention partials ----------------
#define CH 16
__global__ __launch_bounds__(128) void attn_part_kernel(
    const float* __restrict__ Qp, int qstride,
    const float* __restrict__ Kp, const float* __restrict__ Vp, int kvstride,
    const float* __restrict__ biasT, int Lk, int S, int step,
    float* __restrict__ pm, float* __restrict__ pl, float* __restrict__ pacc,
    int useBias)
{
    const int b = blockIdx.z, h = blockIdx.y;
    const int sp = blockIdx.x / QT;
    const int qt = blockIdx.x % QT;
    const int tid = threadIdx.x;
    const int q = qt * 128 + tid;
    const bool active = (q < QQ);

    const int ls = sp * step;
    const int le = min(ls + step, Lk);

    u64 q2[HD / 2];
    if (active) {
        const ulonglong2* qp2 = reinterpret_cast<const ulonglong2*>(
            Qp + ((size_t)(b * QQ + q)) * qstride + h * HD);
        #pragma unroll
        for (int i = 0; i < HD / 4; i++) {
            ulonglong2 tv = qp2[i];
            q2[2 * i] = tv.x; q2[2 * i + 1] = tv.y;
        }
    }
    u64 acc2[HD / 2];
    #pragma unroll
    for (int d = 0; d < HD / 2; d++) acc2[d] = 0ull;
    float m = -INFINITY, lsum = 0.f;

    __shared__ __align__(16) float Ks[CH][HD];
    __shared__ __align__(16) float Vs[CH][HD];

    const int lrow = tid >> 3;          // 0..15
    const int lcol = (tid & 7) * 4;     // 0..28

    for (int l0 = ls; l0 < le; l0 += CH) {
        {
            int gr = min(b * Lk + l0 + lrow, BB * Lk - 1);
            const float4* kp = reinterpret_cast<const float4*>(
                Kp + (size_t)gr * kvstride + h * HD + lcol);
            const float4* vp = reinterpret_cast<const float4*>(
                Vp + (size_t)gr * kvstride + h * HD + lcol);
            *reinterpret_cast<float4*>(&Ks[lrow][lcol]) = *kp;
            *reinterpret_cast<float4*>(&Vs[lrow][lcol]) = *vp;
        }
        float bfr[CH];
        if (useBias) {
            #pragma unroll
            for (int li = 0; li < CH; li++)
                bfr[li] = active
                    ? biasT[((size_t)(b * Lk + l0 + li)) * QQ + q] : 0.f;
        }
        __syncthreads();

        if (active) {
            float s[CH];
            #pragma unroll
            for (int li = 0; li < CH; li++) {
                const ulonglong2* K4 = reinterpret_cast<const ulonglong2*>(Ks[li]);
                u64 tacc = 0ull;
                #pragma unroll
                for (int i = 0; i < HD / 4; i++) {
                    ulonglong2 kv = K4[i];
                    fma2(tacc, q2[2 * i], kv.x);
                    fma2(tacc, q2[2 * i + 1], kv.y);
                }
                float lo, hi; upk2(tacc, lo, hi);
                float sc = (lo + hi) * SCALE;
                if (useBias) sc += bfr[li];
                if (l0 + li >= le) sc = -1e30f;
                s[li] = sc;
            }
            float cm = s[0];
            #pragma unroll
            for (int li = 1; li < CH; li++) cm = fmaxf(cm, s[li]);
            if (cm > m) {
                float corr = __expf(m - cm);
                m = cm;
                lsum *= corr;
                u64 c2 = pk2(corr, corr);
                #pragma unroll
                for (int d = 0; d < HD / 2; d++) mul2(acc2[d], c2);
            }
            #pragma unroll
            for (int li = 0; li < CH; li++) {
                float p = __expf(s[li] - m);
                lsum += p;
                u64 p2 = pk2(p, p);
                const ulonglong2* V4 = reinterpret_cast<const ulonglong2*>(Vs[li]);
                #pragma unroll
                for (int i = 0; i < HD / 4; i++) {
                    ulonglong2 vv = V4[i];
                    fma2(acc2[2 * i], p2, vv.x);
                    fma2(acc2[2 * i + 1], p2, vv.y);
                }
            }
        }
        __syncthreads();
    }

    if (active) {
        size_t pidx = (((size_t)(b * HH + h)) * S + sp) * QQ + q;
        pm[pidx] = m;
        pl[pidx] = lsum;
        u64* ap = reinterpret_cast<u64*>(pacc + pidx * HD);
        #pragma unroll
        for (int d = 0; d < HD / 2; d++) ap[d] = acc2[d];
    }
}

// ---------------- split combine (parallel over d-pairs) ----------------
__global__ __launch_bounds__(256) void attn_combine_kernel(
    const float* __restrict__ pm, const float* __restrict__ pl,
    const float* __restrict__ pacc, int S, float* __restrict__ out)
{
    int t = blockIdx.x * 256 + threadIdx.x;
    if (t >= BB * HH * QQ * (HD / 2)) return;
    int dp = t & (HD / 2 - 1);
    int idx = t >> 4;                  // bh*QQ + q index space
    int q = idx % QQ;
    int bh = idx / QQ;
    int b = bh / HH, h = bh % HH;

    float mg = -INFINITY;
    for (int s = 0; s < S; s++)
        mg = fmaxf(mg, pm[((size_t)bh * S + s) * QQ + q]);
    float Lsum = 0.f;
    u64 o = 0ull;
    const u64* base = reinterpret_cast<const u64*>(pacc);
    for (int s = 0; s < S; s++) {
        size_t pidx = ((size_t)bh * S + s) * QQ + q;
        float w = __expf(pm[pidx] - mg);
        Lsum += pl[pidx] * w;
        u64 a = base[pidx * (HD / 2) + dp];
        fma2(o, pk2(w, w), a);
    }
    float inv = 1.f / Lsum;
    float lo, hi; upk2(o, lo, hi);
    float2* op = reinterpret_cast<float2*>(
        out + ((size_t)(b * QQ + q)) * DD + h * HD + 2 * dp);
    *op = make_float2(lo * inv, hi * inv);
}

// ---------------- host launcher ----------------
static inline int cdiv(int a, int b) { return (a + b - 1) / b; }

extern "C" void kernel_launch(void* const* d_in, const int* in_sizes, int n_in,
                              void* d_out, int out_size)
{
    const float* queries   = (const float*)d_in[0];
    const float* memory    = (const float*)d_in[1];
    const float* memory_pos= (const float*)d_in[2];
    const float* query_pos = (const float*)d_in[3];
    const float* sa_in_w   = (const float*)d_in[4];
    const float* sa_in_b   = (const float*)d_in[5];
    const float* sa_out_w  = (const float*)d_in[6];
    const float* sa_out_b  = (const float*)d_in[7];
    const float* norm1_g   = (const float*)d_in[8];
    const float* norm1_b   = (const float*)d_in[9];
    const float* q_w       = (const float*)d_in[10];
    const float* q_b       = (const float*)d_in[11];
    const float* k_w       = (const float*)d_in[12];
    const float* k_b       = (const float*)d_in[13];
    const float* v_w       = (const float*)d_in[14];
    const float* v_b       = (const float*)d_in[15];
    const float* o_w       = (const float*)d_in[16];
    const float* o_b       = (const float*)d_in[17];
    const float* norm2_g   = (const float*)d_in[18];
    const float* norm2_b   = (const float*)d_in[19];
    const float* beta      = (const float*)d_in[20];
    const float* dk_w1     = (const float*)d_in[21];
    const float* dk_b1     = (const float*)d_in[22];
    const float* dk_w2     = (const float*)d_in[23];
    const float* dk_b2     = (const float*)d_in[24];
    const float* ffn_w1    = (const float*)d_in[25];
    const float* ffn_b1    = (const float*)d_in[26];
    const float* ffn_w2    = (const float*)d_in[27];
    const float* ffn_b2    = (const float*)d_in[28];
    const float* norm3_g   = (const float*)d_in[29];
    const float* norm3_b   = (const float*)d_in[30];

    float *g_qkv, *g_sa, *g_tmp, *g_x1, *g_x2, *g_q, *g_k, *g_v, *g_bias,
          *g_ca, *g_ffn, *g_part, *g_pm, *g_pl, *g_pacc;
    cudaGetSymbolAddress((void**)&g_qkv,  s_qkv);
    cudaGetSymbolAddress((void**)&g_sa,   s_sa);
    cudaGetSymbolAddress((void**)&g_tmp,  s_tmp);
    cudaGetSymbolAddress((void**)&g_x1,   s_x1);
    cudaGetSymbolAddress((void**)&g_x2,   s_x2);
    cudaGetSymbolAddress((void**)&g_q,    s_q);
    cudaGetSymbolAddress((void**)&g_k,    s_k);
    cudaGetSymbolAddress((void**)&g_v,    s_v);
    cudaGetSymbolAddress((void**)&g_bias, s_bias);
    cudaGetSymbolAddress((void**)&g_ca,   s_ca);
    cudaGetSymbolAddress((void**)&g_ffn,  s_ffn);
    cudaGetSymbolAddress((void**)&g_part, s_part);
    cudaGetSymbolAddress((void**)&g_pm,   s_pm);
    cudaGetSymbolAddress((void**)&g_pl,   s_pl);
    cudaGetSymbolAddress((void**)&g_pacc, s_pacc);

    const int Mq = BB * QQ;   // 2400
    const int Mm = BB * LL;   // 8192
    const int NCOMB = BB * HH * QQ * (HD / 2);

    // 1) self-attn packed in-proj [2400,768]
    gemm_tf32_kernel<2><<<dim3(3 * DD / 64, cdiv(Mq, 128), 1), 256>>>(
        queries, sa_in_w, sa_in_b, g_qkv, Mq, 3 * DD, DD, 0);

    // GASA geometric bias (independent — launch early)
    gasa_bias_kernel<<<dim3(QT, LL, BB), 128>>>(
        query_pos, memory_pos, dk_w1, dk_b1, dk_w2, dk_b2, beta, g_bias);

    // 2) self-attention (no bias), split-L S=4
    {
        int S = 4, step = cdiv(QQ, S * CH) * CH;   // 160
        attn_part_kernel<<<dim3(QT * S, HH, BB), 128>>>(
            g_qkv, 3 * DD, g_qkv + DD, g_qkv + 2 * DD, 3 * DD,
            nullptr, QQ, S, step, g_pm, g_pl, g_pacc, 0);
        attn_combine_kernel<<<cdiv(NCOMB, 256), 256>>>(g_pm, g_pl, g_pacc, S, g_sa);
    }

    // 3) SA out-proj + LN1
    gemm_tf32_kernel<1><<<dim3(DD / 64, cdiv(Mq, 64), 1), 256>>>(
        g_sa, sa_out_w, sa_out_b, g_tmp, Mq, DD, DD, 0);
    ln_kernel<<<Mq, 256>>>(queries, g_tmp, norm1_g, norm1_b, g_x1);

    // 4) cross projections
    gemm_tf32_kernel<1><<<dim3(DD / 64, cdiv(Mq, 64), 1), 256>>>(
        g_x1, q_w, q_b, g_q, Mq, DD, DD, 0);
    gemm_tf32_kernel<2><<<dim3(DD / 64, cdiv(Mm, 128), 1), 256>>>(
        memory, k_w, k_b, g_k, Mm, DD, DD, 0);
    gemm_tf32_kernel<2><<<dim3(DD / 64, cdiv(Mm, 128), 1), 256>>>(
        memory, v_w, v_b, g_v, Mm, DD, DD, 0);

    // 5) cross-attention with bias, split-L S=8 (step 256)
    {
        int S = 8, step = cdiv(LL, S * CH) * CH;
        attn_part_kernel<<<dim3(QT * S, HH, BB), 128>>>(
            g_q, DD, g_k, g_v, DD, g_bias, LL, S, step, g_pm, g_pl, g_pacc, 1);
        attn_combine_kernel<<<cdiv(NCOMB, 256), 256>>>(g_pm, g_pl, g_pacc, S, g_ca);
    }

    // 6) O proj + LN2
    gemm_tf32_kernel<1><<<dim3(DD / 64, cdiv(Mq, 64), 1), 256>>>(
        g_ca, o_w, o_b, g_tmp, Mq, DD, DD, 0);
    ln_kernel<<<Mq, 256>>>(g_x1, g_tmp, norm2_g, norm2_b, g_x2);

    // 7) FFN1 (relu)
    gemm_tf32_kernel<2><<<dim3(DFF / 64, cdiv(Mq, 128), 1), 256>>>(
        g_x2, ffn_w1, ffn_b1, g_ffn, Mq, DFF, DD, 1);

    // 8) FFN2 split-K=4 partials + fused combine in LN3 -> output
    gemm_tf32_kernel<1><<<dim3(DD / 64, cdiv(Mq, 64), 4), 256>>>(
        g_ffn, ffn_w2, ffn_b2, g_part, Mq, DD, DFF, 0);
    ln_split_kernel<<<Mq, 256>>>(g_x2, g_part, ffn_b2, norm3_g, norm3_b,
                                 (float*)d_out, 4);
}

// round 5
// speedup vs baseline: 3.7854x; 1.4050x over previous
#include <cuda_runtime.h>
#include <cuda_bf16.h>
#include <math.h>
#include <stdint.h>

// ---------------- problem constants ----------------
#define BB 4
#define QQ 600
#define LL 2048
#define DD 256
#define HH 8
#define HD 32
#define DFF 2048
#define KD 32
#define SCALE 0.17677669529663687f   // 32^-0.5
#define NQT 10                       // ceil(600/64) 64-query tiles

typedef unsigned long long u64;

// ---------------- helpers ----------------
__device__ __forceinline__ uint32_t f2tf32(float x) {
    uint32_t u; asm("cvt.rna.tf32.f32 %0, %1;" : "=r"(u) : "f"(x)); return u;
}
__device__ __forceinline__ void mma8(float c[4], uint32_t a0, uint32_t a1,
                                     uint32_t a2, uint32_t a3,
                                     uint32_t b0, uint32_t b1) {
    asm("mma.sync.aligned.m16n8k8.row.col.f32.tf32.tf32.f32 "
        "{%0,%1,%2,%3},{%4,%5,%6,%7},{%8,%9},{%0,%1,%2,%3};"
        : "+f"(c[0]), "+f"(c[1]), "+f"(c[2]), "+f"(c[3])
        : "r"(a0), "r"(a1), "r"(a2), "r"(a3), "r"(b0), "r"(b1));
}
__device__ __forceinline__ void cp16(uint32_t dst, const void* src, int srcsize) {
    asm volatile("cp.async.ca.shared.global [%0], [%1], 16, %2;"
                 :: "r"(dst), "l"(src), "r"(srcsize));
}
__device__ __forceinline__ void cp_commit() {
    asm volatile("cp.async.commit_group;");
}
__device__ __forceinline__ void cp_wait1() {
    asm volatile("cp.async.wait_group 1;");
}

// ---------------- scratch (device globals) ----------------
__device__ float s_qkv [BB*QQ*3*DD];
__device__ float s_sa  [BB*QQ*DD];
__device__ float s_tmp [BB*QQ*DD];
__device__ float s_x1  [BB*QQ*DD];
__device__ float s_x2  [BB*QQ*DD];
__device__ float s_q   [BB*QQ*DD];
__device__ float s_k   [BB*LL*DD];
__device__ float s_v   [BB*LL*DD];
__device__ float s_bias[BB*LL*QQ];           // beta * clipped bias, [B, L, Q]
__device__ float s_ca  [BB*QQ*DD];
__device__ float s_ffn [BB*QQ*DFF];
__device__ float s_part[4*BB*QQ*DD];         // ffn2 split-K partials
__device__ float s_pm  [BB*HH*8*QQ];
__device__ float s_pl  [BB*HH*8*QQ];
__device__ float s_pacc[BB*HH*8*QQ*HD];

// ---------------- TF32 tensor-core GEMM (cp.async double-buffered) --------
#define KPAD 20

template<int MF>
__global__ __launch_bounds__(256) void gemm_tf32_kernel(
    const float* __restrict__ A, const float* __restrict__ W,
    const float* __restrict__ bias, float* __restrict__ C,
    int M, int N, int K, int relu)
{
    __shared__ __align__(16) uint32_t As[2][64 * MF][KPAD];
    __shared__ __align__(16) uint32_t Ws[2][64][KPAD];

    const int tid = threadIdx.x;
    const int lane = tid & 31;
    const int w = tid >> 5;
    const int wm = w & 3;
    const int wn = w >> 2;
    const int g = lane >> 2;
    const int t = lane & 3;

    const int m0 = blockIdx.y * (64 * MF);
    const int n0 = blockIdx.x * 64;

    const int nsplit = gridDim.z;
    const int Klen = K / nsplit;
    const int kstart = blockIdx.z * Klen;
    float* Cout = (nsplit > 1) ? (C + (size_t)blockIdx.z * M * N) : C;

    const int lr = tid >> 2;
    const int kc = (tid & 3) * 4;

    const uint32_t as_base = (uint32_t)__cvta_generic_to_shared(&As[0][0][0]);
    const uint32_t ws_base = (uint32_t)__cvta_generic_to_shared(&Ws[0][0][0]);

    float acc[MF][4][4];
    #pragma unroll
    for (int i = 0; i < MF; i++)
        #pragma unroll
        for (int j = 0; j < 4; j++)
            #pragma unroll
            for (int e = 0; e < 4; e++) acc[i][j][e] = 0.f;

    const int m_warp = wm * (16 * MF);
    const int n_warp = wn * 32;
    const int nIter = Klen / 16;

    auto load_stage = [&](int st, int it) {
        const int kg = kstart + it * 16 + kc;
        #pragma unroll
        for (int half = 0; half < MF; half++) {
            int r = lr + half * 64;
            int arow = m0 + r;
            uint32_t dst = as_base + ((st * (64 * MF) + r) * KPAD + kc) * 4;
            const float* src = A + (size_t)arow * K + kg;
            cp16(dst, src, (arow < M) ? 16 : 0);
        }
        {
            uint32_t dst = ws_base + ((st * 64 + lr) * KPAD + kc) * 4;
            const float* src = W + (size_t)(n0 + lr) * K + kg;
            cp16(dst, src, 16);
        }
        cp_commit();
    };

    load_stage(0, 0);

    for (int it = 0; it < nIter; it++) {
        if (it + 1 < nIter) load_stage((it + 1) & 1, it + 1);
        else cp_commit();
        cp_wait1();
        __syncthreads();

        const int st = it & 1;
        #pragma unroll
        for (int kk = 0; kk < 16; kk += 8) {
            uint32_t b0[4], b1[4];
            #pragma unroll
            for (int ni = 0; ni < 4; ni++) {
                b0[ni] = Ws[st][n_warp + ni * 8 + g][kk + t];
                b1[ni] = Ws[st][n_warp + ni * 8 + g][kk + t + 4];
            }
            #pragma unroll
            for (int mi = 0; mi < MF; mi++) {
                int mb = m_warp + mi * 16;
                uint32_t a0 = As[st][mb + g][kk + t];
                uint32_t a1 = As[st][mb + g + 8][kk + t];
                uint32_t a2 = As[st][mb + g][kk + t + 4];
                uint32_t a3 = As[st][mb + g + 8][kk + t + 4];
                #pragma unroll
                for (int ni = 0; ni < 4; ni++)
                    mma8(acc[mi][ni], a0, a1, a2, a3, b0[ni], b1[ni]);
            }
        }
        __syncthreads();
    }

    #pragma unroll
    for (int mi = 0; mi < MF; mi++) {
        #pragma unroll
        for (int ni = 0; ni < 4; ni++) {
            int col = n0 + n_warp + ni * 8 + 2 * t;
            float bz0 = 0.f, bz1 = 0.f;
            if (nsplit == 1) { bz0 = bias[col]; bz1 = bias[col + 1]; }
            int r0 = m0 + m_warp + mi * 16 + g;
            int r1 = r0 + 8;
            float v0 = acc[mi][ni][0] + bz0, v1 = acc[mi][ni][1] + bz1;
            float v2 = acc[mi][ni][2] + bz0, v3 = acc[mi][ni][3] + bz1;
            if (relu) {
                v0 = fmaxf(v0, 0.f); v1 = fmaxf(v1, 0.f);
                v2 = fmaxf(v2, 0.f); v3 = fmaxf(v3, 0.f);
            }
            if (r0 < M) *reinterpret_cast<float2*>(Cout + (size_t)r0 * N + col) = make_float2(v0, v1);
            if (r1 < M) *reinterpret_cast<float2*>(Cout + (size_t)r1 * N + col) = make_float2(v2, v3);
        }
    }
}

// ---------------- LayerNorm helpers ----------------
__device__ __forceinline__ void ln_core(float v, int tid, const float* g,
                                        const float* bt, float* out, size_t row)
{
    float s1 = v, s2 = v * v;
    #pragma unroll
    for (int o = 16; o > 0; o >>= 1) {
        s1 += __shfl_xor_sync(0xffffffffu, s1, o);
        s2 += __shfl_xor_sync(0xffffffffu, s2, o);
    }
    __shared__ float r1[8], r2[8];
    int wid = tid >> 5, lane = tid & 31;
    if (lane == 0) { r1[wid] = s1; r2[wid] = s2; }
    __syncthreads();
    if (tid < 32) {
        float a = (lane < 8) ? r1[lane] : 0.f;
        float b = (lane < 8) ? r2[lane] : 0.f;
        #pragma unroll
        for (int o = 4; o > 0; o >>= 1) {
            a += __shfl_xor_sync(0xffffffffu, a, o);
            b += __shfl_xor_sync(0xffffffffu, b, o);
        }
        if (lane == 0) { r1[0] = a; r2[0] = b; }
    }
    __syncthreads();
    float mean = r1[0] * (1.f / DD);
    float var = r2[0] * (1.f / DD) - mean * mean;
    out[row * DD + tid] = (v - mean) * rsqrtf(var + 1e-5f) * g[tid] + bt[tid];
}

__global__ __launch_bounds__(256) void ln_kernel(
    const float* __restrict__ A, const float* __restrict__ R,
    const float* __restrict__ g, const float* __restrict__ bt,
    float* __restrict__ out)
{
    const size_t row = blockIdx.x;
    const int tid = threadIdx.x;
    float v = A[row * DD + tid] + R[row * DD + tid];
    ln_core(v, tid, g, bt, out, row);
}

__global__ __launch_bounds__(256) void ln_split_kernel(
    const float* __restrict__ X, const float* __restrict__ parts,
    const float* __restrict__ fbias,
    const float* __restrict__ g, const float* __restrict__ bt,
    float* __restrict__ out, int nsplit)
{
    const size_t row = blockIdx.x;
    const int tid = threadIdx.x;
    const size_t stride = (size_t)BB * QQ * DD;
    float f = fbias[tid];
    for (int s = 0; s < nsplit; s++) f += parts[s * stride + row * DD + tid];
    float v = X[row * DD + tid] + f;
    ln_core(v, tid, g, bt, out, row);
}

// ---------------- GASA geometric bias ----------------
__global__ __launch_bounds__(128) void gasa_bias_kernel(
    const float* __restrict__ qpos, const float* __restrict__ mpos,
    const float* __restrict__ w1, const float* __restrict__ b1,
    const float* __restrict__ w2, const float* __restrict__ b2,
    const float* __restrict__ betap, float* __restrict__ biasT)
{
    const int b = blockIdx.z;
    const int l = blockIdx.y;
    const int q = blockIdx.x * 128 + threadIdx.x;

    __shared__ float sw1[KD], sb1[KD], sw2[KD], smp[3];
    if (threadIdx.x < KD) {
        sw1[threadIdx.x] = w1[threadIdx.x];
        sb1[threadIdx.x] = b1[threadIdx.x];
        sw2[threadIdx.x] = w2[threadIdx.x];
    }
    if (threadIdx.x < 3)
        smp[threadIdx.x] = mpos[((size_t)b * LL + l) * 3 + threadIdx.x];
    __syncthreads();

    if (q >= QQ) return;
    const float* qp = qpos + ((size_t)b * QQ + q) * 3;
    float dx = qp[0] - smp[0], dy = qp[1] - smp[1], dz = qp[2] - smp[2];
    float dist = sqrtf(fmaxf(dx * dx + dy * dy + dz * dz, 0.f));

    float s = 0.f;
    #pragma unroll
    for (int k = 0; k < KD; k++) {
        float h = fmaxf(dist * sw1[k] + sb1[k], 0.f);
        s += h * sw2[k];
    }
    s += b2[0];
    s = fminf(fmaxf(s, -10.f), 0.f);
    biasT[((size_t)b * LL + l) * QQ + q] = s * betap[0];
}

// ---------------- tensor-core flash attention partials ----------------
// Block: 128 threads = 4 warps; warp owns 16 queries; block = 64 queries.
// Chunk: 16 keys. Scores & PV on mma.m16n8k8.tf32.
// grid.x = NQT * S, grid.y = H, grid.z = B.
__global__ __launch_bounds__(128) void attn_mma_kernel(
    const float* __restrict__ Qp, int qstride,
    const float* __restrict__ Kp, const float* __restrict__ Vp, int kvstride,
    const float* __restrict__ biasT, int Lk, int S, int step,
    float* __restrict__ pm, float* __restrict__ pl, float* __restrict__ pacc,
    int useBias)
{
    const int b = blockIdx.z, h = blockIdx.y;
    const int sp = blockIdx.x / NQT;
    const int qt = blockIdx.x % NQT;
    const int tid = threadIdx.x;
    const int lane = tid & 31;
    const int warp = tid >> 5;
    const int g = lane >> 2;
    const int t = lane & 3;

    const int q0 = qt * 64 + warp * 16;          // warp's base query
    const int qg  = q0 + g;                      // row 0 of m-frag
    const int qg8 = q0 + g + 8;                  // row 1 of m-frag
    const int qgc  = min(qg, QQ - 1);
    const int qg8c = min(qg8, QQ - 1);

    const int ls = sp * step;
    const int le = min(ls + step, Lk);

    // --- Q a-fragments (pre-scaled, tf32) ---
    uint32_t qa[4][4];                           // [kstep][reg]
    {
        const float* q0p = Qp + ((size_t)(b * QQ + qgc)) * qstride + h * HD;
        const float* q1p = Qp + ((size_t)(b * QQ + qg8c)) * qstride + h * HD;
        #pragma unroll
        for (int ks = 0; ks < 4; ks++) {
            qa[ks][0] = f2tf32(q0p[ks * 8 + t] * SCALE);
            qa[ks][1] = f2tf32(q1p[ks * 8 + t] * SCALE);
            qa[ks][2] = f2tf32(q0p[ks * 8 + t + 4] * SCALE);
            qa[ks][3] = f2tf32(q1p[ks * 8 + t + 4] * SCALE);
        }
    }

    __shared__ uint32_t Ks[16][36];              // [key][d], pad 36: conflict-free frag reads
    __shared__ uint32_t Vt[HD][17];              // [d][key], pad 17: conflict-free stores

    float oacc[4][4];                            // O[q][d] c-frags, nf over d
    #pragma unroll
    for (int i = 0; i < 4; i++)
        #pragma unroll
        for (int j = 0; j < 4; j++) oacc[i][j] = 0.f;
    float om0 = -INFINITY, om1 = -INFINITY;
    float ol0 = 0.f, ol1 = 0.f;

    const int key_l = tid >> 3;                  // 0..15
    const int d0 = (tid & 7) * 4;                // 0..28

    for (int l0 = ls; l0 < le; l0 += 16) {
        // --- cooperative K/V chunk load (fp32 -> tf32) ---
        {
            int grow = b * Lk + min(l0 + key_l, Lk - 1);
            float4 kv = *reinterpret_cast<const float4*>(
                Kp + (size_t)grow * kvstride + h * HD + d0);
            uint4 ku = make_uint4(f2tf32(kv.x), f2tf32(kv.y), f2tf32(kv.z), f2tf32(kv.w));
            *reinterpret_cast<uint4*>(&Ks[key_l][d0]) = ku;
            float4 vv = *reinterpret_cast<const float4*>(
                Vp + (size_t)grow * kvstride + h * HD + d0);
            Vt[d0 + 0][key_l] = f2tf32(vv.x);
            Vt[d0 + 1][key_l] = f2tf32(vv.y);
            Vt[d0 + 2][key_l] = f2tf32(vv.z);
            Vt[d0 + 3][key_l] = f2tf32(vv.w);
        }
        __syncthreads();

        // --- scores S = Qs @ K^T : c-frags sc[nf][4], cols nf*8 + {2t,2t+1} ---
        float sc[2][4];
        #pragma unroll
        for (int nf = 0; nf < 2; nf++) {
            sc[nf][0] = sc[nf][1] = sc[nf][2] = sc[nf][3] = 0.f;
            #pragma unroll
            for (int ks = 0; ks < 4; ks++) {
                uint32_t b0 = Ks[nf * 8 + g][ks * 8 + t];
                uint32_t b1 = Ks[nf * 8 + g][ks * 8 + t + 4];
                mma8(sc[nf], qa[ks][0], qa[ks][1], qa[ks][2], qa[ks][3], b0, b1);
            }
        }

        // --- bias + key-bound mask ---
        #pragma unroll
        for (int nf = 0; nf < 2; nf++) {
            int kc = l0 + nf * 8 + 2 * t;
            if (useBias) {
                const float* bp0 = biasT + ((size_t)(b * Lk + min(kc, Lk - 1))) * QQ;
                const float* bp1 = biasT + ((size_t)(b * Lk + min(kc + 1, Lk - 1))) * QQ;
                sc[nf][0] += bp0[qgc];
                sc[nf][1] += bp1[qgc];
                sc[nf][2] += bp0[qg8c];
                sc[nf][3] += bp1[qg8c];
            }
            if (kc >= le)     { sc[nf][0] = -1e30f; sc[nf][2] = -1e30f; }
            if (kc + 1 >= le) { sc[nf][1] = -1e30f; sc[nf][3] = -1e30f; }
        }

        // --- row max (quad reduce) + online rescale ---
        float mx0 = fmaxf(fmaxf(sc[0][0], sc[0][1]), fmaxf(sc[1][0], sc[1][1]));
        float mx1 = fmaxf(fmaxf(sc[0][2], sc[0][3]), fmaxf(sc[1][2], sc[1][3]));
        mx0 = fmaxf(mx0, __shfl_xor_sync(0xffffffffu, mx0, 1));
        mx0 = fmaxf(mx0, __shfl_xor_sync(0xffffffffu, mx0, 2));
        mx1 = fmaxf(mx1, __shfl_xor_sync(0xffffffffu, mx1, 1));
        mx1 = fmaxf(mx1, __shfl_xor_sync(0xffffffffu, mx1, 2));

        float nm0 = fmaxf(om0, mx0), nm1 = fmaxf(om1, mx1);
        float cr0 = __expf(om0 - nm0), cr1 = __expf(om1 - nm1);
        om0 = nm0; om1 = nm1;
        ol0 *= cr0; ol1 *= cr1;
        #pragma unroll
        for (int nd = 0; nd < 4; nd++) {
            oacc[nd][0] *= cr0; oacc[nd][1] *= cr0;
            oacc[nd][2] *= cr1; oacc[nd][3] *= cr1;
        }

        // --- P = exp(S - m) ---
        #pragma unroll
        for (int nf = 0; nf < 2; nf++) {
            sc[nf][0] = __expf(sc[nf][0] - nm0);
            sc[nf][1] = __expf(sc[nf][1] - nm0);
            sc[nf][2] = __expf(sc[nf][2] - nm1);
            sc[nf][3] = __expf(sc[nf][3] - nm1);
            ol0 += sc[nf][0] + sc[nf][1];
            ol1 += sc[nf][2] + sc[nf][3];
        }

        // --- P transpose (c-frag -> a-frag) + PV mma ---
        #pragma unroll
        for (int ks = 0; ks < 2; ks++) {
            int src0 = t >> 1, src1 = (t >> 1) + 2;
            float v0 = __shfl_sync(0xffffffffu, sc[ks][0], src0, 4);
            float v1 = __shfl_sync(0xffffffffu, sc[ks][1], src0, 4);
            float v2 = __shfl_sync(0xffffffffu, sc[ks][2], src0, 4);
            float v3 = __shfl_sync(0xffffffffu, sc[ks][3], src0, 4);
            float w0 = __shfl_sync(0xffffffffu, sc[ks][0], src1, 4);
            float w1 = __shfl_sync(0xffffffffu, sc[ks][1], src1, 4);
            float w2 = __shfl_sync(0xffffffffu, sc[ks][2], src1, 4);
            float w3 = __shfl_sync(0xffffffffu, sc[ks][3], src1, 4);
            bool odd = (t & 1);
            uint32_t pa0 = f2tf32(odd ? v1 : v0);   // P[g][t]
            uint32_t pa1 = f2tf32(odd ? v3 : v2);   // P[g+8][t]
            uint32_t pa2 = f2tf32(odd ? w1 : w0);   // P[g][t+4]
            uint32_t pa3 = f2tf32(odd ? w3 : w2);   // P[g+8][t+4]
            #pragma unroll
            for (int nd = 0; nd < 4; nd++) {
                uint32_t b0 = Vt[nd * 8 + g][ks * 8 + t];
                uint32_t b1 = Vt[nd * 8 + g][ks * 8 + t + 4];
                mma8(oacc[nd], pa0, pa1, pa2, pa3, b0, b1);
            }
        }
        __syncthreads();
    }

    // --- epilogue: quad-reduce lsum, write partials ---
    ol0 += __shfl_xor_sync(0xffffffffu, ol0, 1);
    ol0 += __shfl_xor_sync(0xffffffffu, ol0, 2);
    ol1 += __shfl_xor_sync(0xffffffffu, ol1, 1);
    ol1 += __shfl_xor_sync(0xffffffffu, ol1, 2);

    size_t pbase = ((size_t)((b * HH + h) * S + sp)) * QQ;
    if (qg < QQ) {
        if (t == 0) { pm[pbase + qg] = om0; pl[pbase + qg] = ol0; }
        float* ap = pacc + (pbase + qg) * HD;
        #pragma unroll
        for (int nd = 0; nd < 4; nd++)
            *reinterpret_cast<float2*>(ap + nd * 8 + 2 * t) =
                make_float2(oacc[nd][0], oacc[nd][1]);
    }
    if (qg8 < QQ) {
        if (t == 0) { pm[pbase + qg8] = om1; pl[pbase + qg8] = ol1; }
        float* ap = pacc + (pbase + qg8) * HD;
        #pragma unroll
        for (int nd = 0; nd < 4; nd++)
            *reinterpret_cast<float2*>(ap + nd * 8 + 2 * t) =
                make_float2(oacc[nd][2], oacc[nd][3]);
    }
}

// ---------------- split combine (parallel over d-pairs) ----------------
__global__ __launch_bounds__(256) void attn_combine_kernel(
    const float* __restrict__ pm, const float* __restrict__ pl,
    const float* __restrict__ pacc, int S, float* __restrict__ out)
{
    int tt = blockIdx.x * 256 + threadIdx.x;
    if (tt >= BB * HH * QQ * (HD / 2)) return;
    int dp = tt & (HD / 2 - 1);
    int idx = tt >> 4;
    int q = idx % QQ;
    int bh = idx / QQ;
    int b = bh / HH, h = bh % HH;

    float mg = -INFINITY;
    for (int s = 0; s < S; s++)
        mg = fmaxf(mg, pm[((size_t)bh * S + s) * QQ + q]);
    float Lsum = 0.f;
    float olo = 0.f, ohi = 0.f;
    for (int s = 0; s < S; s++) {
        size_t pidx = ((size_t)bh * S + s) * QQ + q;
        float w = __expf(pm[pidx] - mg);
        Lsum += pl[pidx] * w;
        float2 a = *reinterpret_cast<const float2*>(pacc + pidx * HD + 2 * dp);
        olo += w * a.x; ohi += w * a.y;
    }
    float inv = 1.f / Lsum;
    float2* op = reinterpret_cast<float2*>(
        out + ((size_t)(b * QQ + q)) * DD + h * HD + 2 * dp);
    *op = make_float2(olo * inv, ohi * inv);
}

// ---------------- host launcher ----------------
static inline int cdiv(int a, int b) { return (a + b - 1) / b; }

extern "C" void kernel_launch(void* const* d_in, const int* in_sizes, int n_in,
                              void* d_out, int out_size)
{
    const float* queries   = (const float*)d_in[0];
    const float* memory    = (const float*)d_in[1];
    const float* memory_pos= (const float*)d_in[2];
    const float* query_pos = (const float*)d_in[3];
    const float* sa_in_w   = (const float*)d_in[4];
    const float* sa_in_b   = (const float*)d_in[5];
    const float* sa_out_w  = (const float*)d_in[6];
    const float* sa_out_b  = (const float*)d_in[7];
    const float* norm1_g   = (const float*)d_in[8];
    const float* norm1_b   = (const float*)d_in[9];
    const float* q_w       = (const float*)d_in[10];
    const float* q_b       = (const float*)d_in[11];
    const float* k_w       = (const float*)d_in[12];
    const float* k_b       = (const float*)d_in[13];
    const float* v_w       = (const float*)d_in[14];
    const float* v_b       = (const float*)d_in[15];
    const float* o_w       = (const float*)d_in[16];
    const float* o_b       = (const float*)d_in[17];
    const float* norm2_g   = (const float*)d_in[18];
    const float* norm2_b   = (const float*)d_in[19];
    const float* beta      = (const float*)d_in[20];
    const float* dk_w1     = (const float*)d_in[21];
    const float* dk_b1     = (const float*)d_in[22];
    const float* dk_w2     = (const float*)d_in[23];
    const float* dk_b2     = (const float*)d_in[24];
    const float* ffn_w1    = (const float*)d_in[25];
    const float* ffn_b1    = (const float*)d_in[26];
    const float* ffn_w2    = (const float*)d_in[27];
    const float* ffn_b2    = (const float*)d_in[28];
    const float* norm3_g   = (const float*)d_in[29];
    const float* norm3_b   = (const float*)d_in[30];

    float *g_qkv, *g_sa, *g_tmp, *g_x1, *g_x2, *g_q, *g_k, *g_v, *g_bias,
          *g_ca, *g_ffn, *g_part, *g_pm, *g_pl, *g_pacc;
    cudaGetSymbolAddress((void**)&g_qkv,  s_qkv);
    cudaGetSymbolAddress((void**)&g_sa,   s_sa);
    cudaGetSymbolAddress((void**)&g_tmp,  s_tmp);
    cudaGetSymbolAddress((void**)&g_x1,   s_x1);
    cudaGetSymbolAddress((void**)&g_x2,   s_x2);
    cudaGetSymbolAddress((void**)&g_q,    s_q);
    cudaGetSymbolAddress((void**)&g_k,    s_k);
    cudaGetSymbolAddress((void**)&g_v,    s_v);
    cudaGetSymbolAddress((void**)&g_bias, s_bias);
    cudaGetSymbolAddress((void**)&g_ca,   s_ca);
    cudaGetSymbolAddress((void**)&g_ffn,  s_ffn);
    cudaGetSymbolAddress((void**)&g_part, s_part);
    cudaGetSymbolAddress((void**)&g_pm,   s_pm);
    cudaGetSymbolAddress((void**)&g_pl,   s_pl);
    cudaGetSymbolAddress((void**)&g_pacc, s_pacc);

    const int Mq = BB * QQ;   // 2400
    const int Mm = BB * LL;   // 8192
    const int NCOMB = BB * HH * QQ * (HD / 2);

    // 1) self-attn packed in-proj [2400,768]
    gemm_tf32_kernel<2><<<dim3(3 * DD / 64, cdiv(Mq, 128), 1), 256>>>(
        queries, sa_in_w, sa_in_b, g_qkv, Mq, 3 * DD, DD, 0);

    // GASA geometric bias (independent — launch early)
    gasa_bias_kernel<<<dim3(cdiv(QQ, 128), LL, BB), 128>>>(
        query_pos, memory_pos, dk_w1, dk_b1, dk_w2, dk_b2, beta, g_bias);

    // 2) self-attention (no bias), split S=2
    {
        int S = 2, step = cdiv(QQ, S * 16) * 16;   // 304
        attn_mma_kernel<<<dim3(NQT * S, HH, BB), 128>>>(
            g_qkv, 3 * DD, g_qkv + DD, g_qkv + 2 * DD, 3 * DD,
            nullptr, QQ, S, step, g_pm, g_pl, g_pacc, 0);
        attn_combine_kernel<<<cdiv(NCOMB, 256), 256>>>(g_pm, g_pl, g_pacc, S, g_sa);
    }

    // 3) SA out-proj + LN1
    gemm_tf32_kernel<1><<<dim3(DD / 64, cdiv(Mq, 64), 1), 256>>>(
        g_sa, sa_out_w, sa_out_b, g_tmp, Mq, DD, DD, 0);
    ln_kernel<<<Mq, 256>>>(queries, g_tmp, norm1_g, norm1_b, g_x1);

    // 4) cross projections
    gemm_tf32_kernel<1><<<dim3(DD / 64, cdiv(Mq, 64), 1), 256>>>(
        g_x1, q_w, q_b, g_q, Mq, DD, DD, 0);
    gemm_tf32_kernel<2><<<dim3(DD / 64, cdiv(Mm, 128), 1), 256>>>(
        memory, k_w, k_b, g_k, Mm, DD, DD, 0);
    gemm_tf32_kernel<2><<<dim3(DD / 64, cdiv(Mm, 128), 1), 256>>>(
        memory, v_w, v_b, g_v, Mm, DD, DD, 0);

    // 5) cross-attention with bias, split S=4 (step 512)
    {
        int S = 4, step = cdiv(LL, S * 16) * 16;   // 512
        attn_mma_kernel<<<dim3(NQT * S, HH, BB), 128>>>(
            g_q, DD, g_k, g_v, DD, g_bias, LL, S, step, g_pm, g_pl, g_pacc, 1);
        attn_combine_kernel<<<cdiv(NCOMB, 256), 256>>>(g_pm, g_pl, g_pacc, S, g_ca);
    }

    // 6) O proj + LN2
    gemm_tf32_kernel<1><<<dim3(DD / 64, cdiv(Mq, 64), 1), 256>>>(
        g_ca, o_w, o_b, g_tmp, Mq, DD, DD, 0);
    ln_kernel<<<Mq, 256>>>(g_x1, g_tmp, norm2_g, norm2_b, g_x2);

    // 7) FFN1 (relu)
    gemm_tf32_kernel<2><<<dim3(DFF / 64, cdiv(Mq, 128), 1), 256>>>(
        g_x2, ffn_w1, ffn_b1, g_ffn, Mq, DFF, DD, 1);

    // 8) FFN2 split-K=4 partials + fused combine in LN3 -> output
    gemm_tf32_kernel<1><<<dim3(DD / 64, cdiv(Mq, 64), 4), 256>>>(
        g_ffn, ffn_w2, ffn_b2, g_part, Mq, DD, DFF, 0);
    ln_split_kernel<<<Mq, 256>>>(g_x2, g_part, ffn_b2, norm3_g, norm3_b,
                                 (float*)d_out, 4);
}